// round 12
// baseline (speedup 1.0000x reference)
#include <cuda_runtime.h>
#include <cuda_bf16.h>
#include <math.h>
#include <stdint.h>

#define BB 8
#define TT 4096
#define DD 256
#define MM 1024
#define CTX 7
#define LL (TT - 1 + CTX)      /* 4102 */
#define LLP 4104               /* padded stride */
#define NN (BB*TT)             /* 32768 */
#define QSIZE (NN*DD)          /* 8388608 */

// ---------------- scratch ----------------------------------------------------
__device__ __align__(16) float2 g_xt2[BB*DD*TT];        // x^T as (tf32hi, lo)
__device__ __align__(16) float2 g_noisy2[BB*DD*LLP];    // noisy ctx-in (hi, lo)
__device__ __align__(16) float2 g_ctx2[BB*DD*TT];       // conv out (hi, lo)
__device__ __align__(16) float g_wch[DD*DD*CTX];        // w_ctx hi, A-frag shuffled
__device__ __align__(16) float g_wcl[DD*DD*CTX];
__device__ __align__(16) float g_w1shh[2*DD*DD];
__device__ __align__(16) float g_w1shl[2*DD*DD];
__device__ __align__(16) float g_w2shh[DD*DD];
__device__ __align__(16) float g_w2shl[DD*DD];
__device__ __align__(16) float g_cur[(size_t)NN*DD];    // fuse1 out, exact fp32
__device__ __align__(16) __nv_bfloat16 g_cur_bh[(size_t)NN*DD];
__device__ __align__(16) __nv_bfloat16 g_cur_bl[(size_t)NN*DD];
__device__ __align__(16) __nv_bfloat16 g_E_bh[MM*DD];
__device__ __align__(16) __nv_bfloat16 g_E_bl[MM*DD];
__device__ __align__(16) float g_G[(size_t)NN*MM];
__device__ __align__(16) float g_ET[DD*MM];
__device__ __align__(16) float g_w2T[2*DD*DD];
__device__ __align__(16) float g_W2E[MM*DD];
__device__ __align__(16) float g_esq[MM];
__device__ float g_scale[BB];
__device__ int   g_idx[NN];
__device__ unsigned int g_hist[MM];
__device__ float g_avgp[MM];

__device__ __forceinline__ float tf32_hi(float v) {
    uint32_t b;
    asm("cvt.rna.tf32.f32 %0, %1;" : "=r"(b) : "f"(v));
    return __uint_as_float(b);
}

#define MMA8(d, a0,a1,a2,a3, b0,b1) \
    asm volatile("mma.sync.aligned.m16n8k8.row.col.f32.tf32.tf32.f32 " \
        "{%0,%1,%2,%3}, {%4,%5,%6,%7}, {%8,%9}, {%0,%1,%2,%3};" \
        : "+f"((d)[0]), "+f"((d)[1]), "+f"((d)[2]), "+f"((d)[3]) \
        : "r"(a0), "r"(a1), "r"(a2), "r"(a3), "r"(b0), "r"(b1))

#define MMA16B(d, a, b) \
    asm volatile("mma.sync.aligned.m16n8k16.row.col.f32.bf16.bf16.f32 " \
        "{%0,%1,%2,%3}, {%4,%5,%6,%7}, {%8,%9}, {%0,%1,%2,%3};" \
        : "+f"((d)[0]), "+f"((d)[1]), "+f"((d)[2]), "+f"((d)[3]) \
        : "r"((a)[0]), "r"((a)[1]), "r"((a)[2]), "r"((a)[3]), "r"((b)[0]), "r"((b)[1]))

// ---------------- small utility kernels -------------------------------------
__global__ void k_zero() {
    int i = blockIdx.x*blockDim.x + threadIdx.x;
    if (i < MM) { g_hist[i] = 0u; g_avgp[i] = 0.f; }
}

__global__ void k_transp(const float* __restrict__ src, int rows, int cols, int which) {
    __shared__ float s[32][33];
    float* dst = (which == 0) ? g_ET : g_w2T;
    int c0 = blockIdx.x*32, r0 = blockIdx.y*32;
    int tx = threadIdx.x, ty = threadIdx.y;
    #pragma unroll
    for (int j = 0; j < 4; j++) {
        int r = r0 + ty + j*8, c = c0 + tx;
        s[ty + j*8][tx] = (r < rows && c < cols) ? src[(size_t)r*cols + c] : 0.f;
    }
    __syncthreads();
    #pragma unroll
    for (int j = 0; j < 4; j++) {
        int c = c0 + ty + j*8, r = r0 + tx;
        if (c < cols && r < rows) dst[(size_t)c*rows + r] = s[tx][ty + j*8];
    }
}

__global__ void k_esq(const float* __restrict__ E) {
    int warp = threadIdx.x >> 5, lane = threadIdx.x & 31;
    int m = blockIdx.x*8 + warp;
    const float* row = E + (size_t)m*DD;
    float s = 0.f;
    for (int c = lane; c < DD; c += 32) { float v = row[c]; s += v*v; }
    #pragma unroll
    for (int o = 16; o > 0; o >>= 1) s += __shfl_down_sync(0xffffffffu, s, o);
    if (lane == 0) g_esq[m] = s;
}

__global__ void k_split_eb(const float* __restrict__ E) {
    int i = blockIdx.x*256 + threadIdx.x;
    float v = E[i];
    __nv_bfloat16 h = __float2bfloat16(v);
    g_E_bh[i] = h;
    g_E_bl[i] = __float2bfloat16(v - __bfloat162float(h));
}

__global__ void k_splitw(const float* __restrict__ wctx) {
    int idx = blockIdx.x*256 + threadIdx.x;       // grid 1792
    int o = idx / (DD*CTX);
    int rem = idx - o*(DD*CTX);
    int i = rem / CTX, kk = rem - i*CTX;
    float v = wctx[idx];
    float h = tf32_hi(v);
    int ic = i >> 3, il = i & 7;
    int otile = o >> 4, oloc = o & 15;
    int lane = (oloc & 7)*4 + (il & 3);
    int reg = (oloc >> 3) + 2*(il >> 2);
    int d = ((ic*7 + kk)*16 + otile)*128 + lane*4 + reg;
    g_wch[d] = h;
    g_wcl[d] = tf32_hi(v - h);
}

__global__ void k_splitw1(const float* __restrict__ wf1) {
    int idx = blockIdx.x*256 + threadIdx.x;       // grid 512
    int o = idx >> 9, k = idx & 511;
    float v = wf1[idx];
    float h = tf32_hi(v);
    int ks = k >> 3, il = k & 7;
    int otile = o >> 4, oloc = o & 15;
    int lane = (oloc & 7)*4 + (il & 3);
    int reg = (oloc >> 3) + 2*(il >> 2);
    int d = (ks*16 + otile)*128 + lane*4 + reg;
    g_w1shh[d] = h;
    g_w1shl[d] = tf32_hi(v - h);
}

__global__ void k_shufw2(const float* __restrict__ wf2) {
    int idx = blockIdx.x*256 + threadIdx.x;       // grid 256
    int o = idx >> 8, k = idx & 255;
    int ic = k >> 3, il = k & 7;
    int otile = o >> 4, oloc = o & 15;
    int lane = (oloc & 7)*4 + (il & 3);
    int reg = (oloc >> 3) + 2*(il >> 2);
    float v = wf2[o*2*DD + DD + k];
    float h = tf32_hi(v);
    int d = (ic*16 + otile)*128 + lane*4 + reg;
    g_w2shh[d] = h;
    g_w2shl[d] = tf32_hi(v - h);
}

__global__ void k_scale(const float* __restrict__ x, const int* __restrict__ epo_p) {
    int b = blockIdx.x;
    const float* xb = x + (size_t)b*TT*DD;
    float s = 0.f;
    int tot = (TT-1)*DD;
    for (int i = threadIdx.x; i < tot; i += blockDim.x) { float v = xb[i]; s += v*v; }
    __shared__ float sm[8];
    #pragma unroll
    for (int o = 16; o > 0; o >>= 1) s += __shfl_down_sync(0xffffffffu, s, o);
    if ((threadIdx.x & 31) == 0) sm[threadIdx.x >> 5] = s;
    __syncthreads();
    if (threadIdx.x == 0) {
        float t = 0.f;
        for (int w = 0; w < 8; w++) t += sm[w];
        int iv = epo_p[0];
        float ef = (iv >= 0 && iv < 100000) ? (float)iv : __int_as_float(iv);
        float sc = sqrtf(t / (float)(DD*LL));
        g_scale[b] = 0.5f * sc * exp2f(-ef * 0.1f);
    }
}

// x -> xt2 (hi,lo) [b][d][t]
__global__ void k_xt(const float* __restrict__ x) {
    __shared__ float s[32][33];
    int b = blockIdx.z, t0 = blockIdx.x*32, d0 = blockIdx.y*32;
    int tx = threadIdx.x, ty = threadIdx.y;
    #pragma unroll
    for (int j = 0; j < 4; j++) {
        int t = t0 + ty + j*8;
        s[ty + j*8][tx] = x[((size_t)b*TT + t)*DD + d0 + tx];
    }
    __syncthreads();
    #pragma unroll
    for (int j = 0; j < 4; j++) {
        int d = d0 + ty + j*8;
        float v = s[tx][ty + j*8];
        float h = tf32_hi(v);
        g_xt2[((size_t)b*DD + d)*TT + t0 + tx] = make_float2(h, tf32_hi(v - h));
    }
}

__global__ void k_noisy(const float* __restrict__ x, const float* __restrict__ noise) {
    __shared__ float s[32][33];
    int b = blockIdx.z, l0 = blockIdx.x*32, i0 = blockIdx.y*32;
    int tx = threadIdx.x, ty = threadIdx.y;
    float coef = g_scale[b];
    #pragma unroll
    for (int j = 0; j < 4; j++) {
        int row = ty + j*8;
        int t = l0 + row - CTX;
        float v = (t >= 0 && t < TT-1) ? x[((size_t)b*TT + t)*DD + i0 + tx] : 0.f;
        s[row][tx] = v;
    }
    __syncthreads();
    #pragma unroll
    for (int j = 0; j < 4; j++) {
        int i = i0 + ty + j*8, l = l0 + tx;
        if (l < LL) {
            float v = s[tx][ty + j*8] + coef * noise[((size_t)b*DD + i)*LL + l];
            float h = tf32_hi(v);
            g_noisy2[((size_t)b*DD + i)*LLP + l] = make_float2(h, tf32_hi(v - h));
        }
    }
}

// ---------------- conv (3xTF32, interleaved X, materialized W) ---------------
#define CV_STG 9344
#define CV_SMEMB (2*CV_STG*4)

__global__ void __launch_bounds__(256, 2) k_conv_tc() {
    extern __shared__ float cs[];
    int tid = threadIdx.x, lane = tid & 31, warp = tid >> 5;
    int warpM = warp >> 2, warpN = warp & 3;
    int t0 = blockIdx.x*128, o0 = blockIdx.y*64, b = blockIdx.z;
    int ot0 = o0 >> 4;

    uint32_t sbase;
    asm("{ .reg .u64 t; cvta.to.shared.u64 t, %1; cvt.u32.u64 %0, t; }" : "=r"(sbase) : "l"(cs));

    auto issue = [&](int ic, int s) {
        const float2* xp = g_noisy2 + ((size_t)(b*DD + ic*8))*LLP + t0;
        uint32_t xd = sbase + (uint32_t)((s*CV_STG)*4);
        for (int idx = tid; idx < 544; idx += 256) {
            int row = idx / 68, q = idx - row*68;
            asm volatile("cp.async.cg.shared.global [%0], [%1], 16;"
                :: "r"(xd + (uint32_t)((row*136 + q*2)*8)), "l"(xp + (size_t)row*LLP + q*2));
        }
        const float* wh = g_wch + ((size_t)(ic*7)*16 + ot0)*128;
        const float* wl = g_wcl + ((size_t)(ic*7)*16 + ot0)*128;
        uint32_t wdh = sbase + (uint32_t)((s*CV_STG + 2176)*4);
        uint32_t wdl = wdh + 3584*4;
        for (int idx = tid; idx < 896; idx += 256) {
            int kk = idx >> 7, q = idx & 127;
            asm volatile("cp.async.cg.shared.global [%0], [%1], 16;"
                :: "r"(wdh + (uint32_t)((kk*512 + q*4)*4)), "l"(wh + kk*2048 + q*4));
            asm volatile("cp.async.cg.shared.global [%0], [%1], 16;"
                :: "r"(wdl + (uint32_t)((kk*512 + q*4)*4)), "l"(wl + kk*2048 + q*4));
        }
        asm volatile("cp.async.commit_group;");
    };

    float c[2][4][4] = {};
    issue(0, 0);
    issue(1, 1);

    for (int ic = 0; ic < 32; ic++) {
        int s = ic & 1;
        if (ic < 31) { asm volatile("cp.async.wait_group 1;"); }
        else         { asm volatile("cp.async.wait_group 0;"); }
        __syncthreads();
        const float2* X2 = (const float2*)(cs + s*CV_STG);
        const float* WH = cs + s*CV_STG + 2176;
        const float* WL = cs + s*CV_STG + 5760;
        int i0v = lane & 3, trow = lane >> 2;

        #pragma unroll
        for (int kk = 0; kk < 7; kk++) {
            uint32_t ah[2][4], al[2][4];
            #pragma unroll
            for (int mf = 0; mf < 2; mf++) {
                float4 vh = *(const float4*)&WH[kk*512 + (warpM*2 + mf)*128 + lane*4];
                float4 vl = *(const float4*)&WL[kk*512 + (warpM*2 + mf)*128 + lane*4];
                ah[mf][0] = __float_as_uint(vh.x); ah[mf][1] = __float_as_uint(vh.y);
                ah[mf][2] = __float_as_uint(vh.z); ah[mf][3] = __float_as_uint(vh.w);
                al[mf][0] = __float_as_uint(vl.x); al[mf][1] = __float_as_uint(vl.y);
                al[mf][2] = __float_as_uint(vl.z); al[mf][3] = __float_as_uint(vl.w);
            }
            uint32_t bh[4][2], bl[4][2];
            #pragma unroll
            for (int nf = 0; nf < 4; nf++) {
                int toff = warpN*32 + nf*8 + trow + kk;
                float2 v0 = X2[i0v*136 + toff];
                float2 v1 = X2[(i0v + 4)*136 + toff];
                bh[nf][0] = __float_as_uint(v0.x); bl[nf][0] = __float_as_uint(v0.y);
                bh[nf][1] = __float_as_uint(v1.x); bl[nf][1] = __float_as_uint(v1.y);
            }
            #pragma unroll
            for (int mf = 0; mf < 2; mf++) {
                #pragma unroll
                for (int nf = 0; nf < 4; nf++) {
                    MMA8(c[mf][nf], ah[mf][0], ah[mf][1], ah[mf][2], ah[mf][3], bh[nf][0], bh[nf][1]);
                    MMA8(c[mf][nf], ah[mf][0], ah[mf][1], ah[mf][2], ah[mf][3], bl[nf][0], bl[nf][1]);
                    MMA8(c[mf][nf], al[mf][0], al[mf][1], al[mf][2], al[mf][3], bh[nf][0], bh[nf][1]);
                }
            }
        }
        __syncthreads();
        if (ic + 2 < 32) issue(ic + 2, s);
    }

    #pragma unroll
    for (int mf = 0; mf < 2; mf++) {
        int r = o0 + warpM*32 + mf*16 + (lane >> 2);
        #pragma unroll
        for (int nf = 0; nf < 4; nf++) {
            int tg = t0 + warpN*32 + nf*8 + (lane & 3)*2;
            float v0 = c[mf][nf][0], v1 = c[mf][nf][1];
            float v2 = c[mf][nf][2], v3 = c[mf][nf][3];
            float h0 = tf32_hi(v0), h1 = tf32_hi(v1), h2 = tf32_hi(v2), h3 = tf32_hi(v3);
            size_t o1 = ((size_t)b*DD + r)*TT + tg;
            size_t o2 = ((size_t)b*DD + r + 8)*TT + tg;
            *(float4*)&g_ctx2[o1] = make_float4(h0, tf32_hi(v0 - h0), h1, tf32_hi(v1 - h1));
            *(float4*)&g_ctx2[o2] = make_float4(h2, tf32_hi(v2 - h2), h3, tf32_hi(v3 - h3));
        }
    }
}

// ---------------- fuse1 on tensor cores (3xTF32, interleaved X) --------------
#define F1_STG 6400
#define F1_SMEMB (2*F1_STG*4)

__global__ void __launch_bounds__(256, 2) k_f1_tc(const float* __restrict__ a1p) {
    extern __shared__ float fs[];
    int tid = threadIdx.x, lane = tid & 31, warp = tid >> 5;
    int warpM = warp >> 2, warpN = warp & 3;
    int t0 = blockIdx.x*128, o0 = blockIdx.y*64, b = blockIdx.z;
    int ot0 = o0 >> 4;

    uint32_t sbase;
    asm("{ .reg .u64 t; cvta.to.shared.u64 t, %1; cvt.u32.u64 %0, t; }" : "=r"(sbase) : "l"(fs));

    auto issue = [&](int cchunk, int s) {
        uint32_t xd = sbase + (uint32_t)((s*F1_STG)*4);
        #pragma unroll
        for (int j = 0; j < 4; j++) {
            int idx = tid + j*256;
            int row = idx >> 6, q = idx & 63;
            int d = cchunk*16 + row;
            const float2* sp = (d < DD) ? (g_xt2 + ((size_t)b*DD + d)*TT + t0)
                                        : (g_ctx2 + ((size_t)b*DD + d - DD)*TT + t0);
            asm volatile("cp.async.cg.shared.global [%0], [%1], 16;"
                :: "r"(xd + (uint32_t)((row*136 + q*2)*8)), "l"(sp + q*2));
        }
        const float* wh = g_w1shh + ((size_t)(cchunk*2)*16 + ot0)*128;
        const float* wl = g_w1shl + ((size_t)(cchunk*2)*16 + ot0)*128;
        uint32_t wdh = sbase + (uint32_t)((s*F1_STG + 4352)*4);
        uint32_t wdl = wdh + 1024*4;
        {
            int sl8 = tid >> 7, q = tid & 127;
            asm volatile("cp.async.cg.shared.global [%0], [%1], 16;"
                :: "r"(wdh + (uint32_t)(tid*16)), "l"(wh + sl8*2048 + q*4));
            asm volatile("cp.async.cg.shared.global [%0], [%1], 16;"
                :: "r"(wdl + (uint32_t)(tid*16)), "l"(wl + sl8*2048 + q*4));
        }
        asm volatile("cp.async.commit_group;");
    };

    float c[2][4][4] = {};
    issue(0, 0);
    issue(1, 1);

    for (int cc = 0; cc < 32; cc++) {
        int s = cc & 1;
        if (cc < 31) { asm volatile("cp.async.wait_group 1;"); }
        else         { asm volatile("cp.async.wait_group 0;"); }
        __syncthreads();
        const float2* X2 = (const float2*)(fs + s*F1_STG);
        const float* WH = fs + s*F1_STG + 4352;
        const float* WL = fs + s*F1_STG + 5376;
        int i0v = lane & 3, trow = lane >> 2;

        #pragma unroll
        for (int sl8 = 0; sl8 < 2; sl8++) {
            uint32_t ah[2][4], al[2][4];
            #pragma unroll
            for (int mf = 0; mf < 2; mf++) {
                float4 vh = *(const float4*)&WH[sl8*512 + (warpM*2 + mf)*128 + lane*4];
                float4 vl = *(const float4*)&WL[sl8*512 + (warpM*2 + mf)*128 + lane*4];
                ah[mf][0] = __float_as_uint(vh.x); ah[mf][1] = __float_as_uint(vh.y);
                ah[mf][2] = __float_as_uint(vh.z); ah[mf][3] = __float_as_uint(vh.w);
                al[mf][0] = __float_as_uint(vl.x); al[mf][1] = __float_as_uint(vl.y);
                al[mf][2] = __float_as_uint(vl.z); al[mf][3] = __float_as_uint(vl.w);
            }
            uint32_t bh[4][2], bl[4][2];
            #pragma unroll
            for (int nf = 0; nf < 4; nf++) {
                int toff = warpN*32 + nf*8 + trow;
                int rbase = sl8*8 + i0v;
                float2 v0 = X2[rbase*136 + toff];
                float2 v1 = X2[(rbase + 4)*136 + toff];
                bh[nf][0] = __float_as_uint(v0.x); bl[nf][0] = __float_as_uint(v0.y);
                bh[nf][1] = __float_as_uint(v1.x); bl[nf][1] = __float_as_uint(v1.y);
            }
            #pragma unroll
            for (int mf = 0; mf < 2; mf++) {
                #pragma unroll
                for (int nf = 0; nf < 4; nf++) {
                    MMA8(c[mf][nf], ah[mf][0], ah[mf][1], ah[mf][2], ah[mf][3], bh[nf][0], bh[nf][1]);
                    MMA8(c[mf][nf], ah[mf][0], ah[mf][1], ah[mf][2], ah[mf][3], bl[nf][0], bl[nf][1]);
                    MMA8(c[mf][nf], al[mf][0], al[mf][1], al[mf][2], al[mf][3], bh[nf][0], bh[nf][1]);
                }
            }
        }
        __syncthreads();
        if (cc + 2 < 32) issue(cc + 2, s);
    }

    float a1 = *a1p;
    #pragma unroll
    for (int mf = 0; mf < 2; mf++) {
        int r = warpM*32 + mf*16 + (lane >> 2);
        #pragma unroll
        for (int nf = 0; nf < 4; nf++) {
            int tg = warpN*32 + nf*8 + (lane & 3)*2;
            float v0 = c[mf][nf][0]; v0 = (v0 >= 0.f) ? v0 : a1*v0;
            float v1 = c[mf][nf][1]; v1 = (v1 >= 0.f) ? v1 : a1*v1;
            float v2 = c[mf][nf][2]; v2 = (v2 >= 0.f) ? v2 : a1*v2;
            float v3 = c[mf][nf][3]; v3 = (v3 >= 0.f) ? v3 : a1*v3;
            *(float2*)&fs[r*130 + tg]       = make_float2(v0, v1);
            *(float2*)&fs[(r + 8)*130 + tg] = make_float2(v2, v3);
        }
    }
    __syncthreads();
    int nl = tid >> 1, half = tid & 1;
    size_t n = (size_t)b*TT + t0 + nl;
    float* cp = g_cur + n*DD + o0 + half*32;
    __nv_bfloat16* bhp = g_cur_bh + n*DD + o0 + half*32;
    __nv_bfloat16* blp = g_cur_bl + n*DD + o0 + half*32;
    #pragma unroll
    for (int j = 0; j < 8; j++) {
        float4 v;
        v.x = fs[(half*32 + j*4 + 0)*130 + nl];
        v.y = fs[(half*32 + j*4 + 1)*130 + nl];
        v.z = fs[(half*32 + j*4 + 2)*130 + nl];
        v.w = fs[(half*32 + j*4 + 3)*130 + nl];
        *(float4*)&cp[j*4] = v;
        float vv[4] = {v.x, v.y, v.z, v.w};
        __nv_bfloat16 bh4[4], bl4[4];
        #pragma unroll
        for (int q = 0; q < 4; q++) {
            bh4[q] = __float2bfloat16(vv[q]);
            bl4[q] = __float2bfloat16(vv[q] - __bfloat162float(bh4[q]));
        }
        *(uint2*)&bhp[j*4] = *(uint2*)bh4;
        *(uint2*)&blp[j*4] = *(uint2*)bl4;
    }
}

// ---------------- W2E GEMM (small) -------------------------------------------
__global__ void __launch_bounds__(256) k_gemm_w2e() {
    __shared__ float sA[16][68];
    __shared__ float sB[16][68];
    int i0 = blockIdx.x*64, j0 = blockIdx.y*64;
    int tid = threadIdx.x;
    int tx = tid & 15, ty = tid >> 4;
    int kl = tid >> 4, nl4 = (tid & 15)*4;
    float acc[4][4] = {};
    for (int kc = 0; kc < DD; kc += 16) {
        *(float4*)&sA[kl][nl4] = *(const float4*)(g_ET  + (size_t)(kc + kl)*MM + i0 + nl4);
        *(float4*)&sB[kl][nl4] = *(const float4*)(g_w2T + (size_t)(kc + kl)*DD + j0 + nl4);
        __syncthreads();
        #pragma unroll
        for (int k = 0; k < 16; k++) {
            float4 av = *(const float4*)&sA[k][4*tx];
            float4 bv = *(const float4*)&sB[k][4*ty];
            float ar[4] = {av.x, av.y, av.z, av.w};
            float br[4] = {bv.x, bv.y, bv.z, bv.w};
            #pragma unroll
            for (int a = 0; a < 4; a++)
                #pragma unroll
                for (int cc = 0; cc < 4; cc++)
                    acc[a][cc] += br[a] * ar[cc];
        }
        __syncthreads();
    }
    #pragma unroll
    for (int cc = 0; cc < 4; cc++) {
        int i = i0 + 4*tx + cc;
        float4 v = make_float4(acc[0][cc], acc[1][cc], acc[2][cc], acc[3][cc]);
        *(float4*)&g_W2E[(size_t)i*DD + j0 + 4*ty] = v;
    }
}

// ---------------- dist GEMM via mma.sync bf16 (3xBF16, k16) ------------------
#define DB_ROWW 20
#define DB_ARRW (128*DB_ROWW)
#define DB_STGW (4*DB_ARRW)
#define DB_SMEMB (2*DB_STGW*4)

__global__ void __launch_bounds__(256, 2) k_dist_b() {
    extern __shared__ uint32_t dsm[];
    int tid = threadIdx.x, lane = tid & 31, warp = tid >> 5;
    int warpM = warp >> 2, warpN = warp & 3;
    int n0 = blockIdx.x*128, m0 = blockIdx.y*128;

    uint32_t sbase;
    asm("{ .reg .u64 t; cvta.to.shared.u64 t, %1; cvt.u32.u64 %0, t; }" : "=r"(sbase) : "l"(dsm));

    const __nv_bfloat16* srcs[4] = {
        g_cur_bh + (size_t)n0*DD, g_cur_bl + (size_t)n0*DD,
        g_E_bh   + (size_t)m0*DD, g_E_bl   + (size_t)m0*DD };

    auto issue = [&](int kc, int s) {
        #pragma unroll
        for (int a = 0; a < 4; a++) {
            uint32_t dstb = sbase + (uint32_t)((s*DB_STGW + a*DB_ARRW)*4);
            #pragma unroll
            for (int j = 0; j < 2; j++) {
                int cid = tid + j*256;
                int row = cid >> 2, q = cid & 3;
                uint32_t dst = dstb + (uint32_t)(row*80 + q*16);
                const __nv_bfloat16* src = srcs[a] + (size_t)row*DD + kc + q*8;
                asm volatile("cp.async.cg.shared.global [%0], [%1], 16;"
                             :: "r"(dst), "l"(src));
            }
        }
        asm volatile("cp.async.commit_group;");
    };

    float c[4][4][4] = {};
    issue(0, 0);

    int gr = lane >> 2, lc = lane & 3;
    for (int it = 0; it < 8; it++) {
        int s = it & 1;
        if (it + 1 < 8) issue((it + 1)*32, s ^ 1);
        if (it + 1 < 8) { asm volatile("cp.async.wait_group 1;"); }
        else            { asm volatile("cp.async.wait_group 0;"); }
        __syncthreads();

        const uint32_t* sAh = dsm + s*DB_STGW;
        const uint32_t* sAl = sAh + DB_ARRW;
        const uint32_t* sBh = sAh + 2*DB_ARRW;
        const uint32_t* sBl = sAh + 3*DB_ARRW;

        #pragma unroll
        for (int ks = 0; ks < 2; ks++) {
            int wb = ks*8 + lc;
            uint32_t ah[4][4], al[4][4], bh[4][2], bl[4][2];
            #pragma unroll
            for (int mf = 0; mf < 4; mf++) {
                int r1 = (warpM*64 + mf*16 + gr)*DB_ROWW, r2 = r1 + 8*DB_ROWW;
                ah[mf][0] = sAh[r1 + wb];     ah[mf][1] = sAh[r2 + wb];
                ah[mf][2] = sAh[r1 + wb + 4]; ah[mf][3] = sAh[r2 + wb + 4];
                al[mf][0] = sAl[r1 + wb];     al[mf][1] = sAl[r2 + wb];
                al[mf][2] = sAl[r1 + wb + 4]; al[mf][3] = sAl[r2 + wb + 4];
            }
            #pragma unroll
            for (int nf = 0; nf < 4; nf++) {
                int rn = (warpN*32 + nf*8 + gr)*DB_ROWW;
                bh[nf][0] = sBh[rn + wb]; bh[nf][1] = sBh[rn + wb + 4];
                bl[nf][0] = sBl[rn + wb]; bl[nf][1] = sBl[rn + wb + 4];
            }
            #pragma unroll
            for (int mf = 0; mf < 4; mf++) {
                #pragma unroll
                for (int nf = 0; nf < 4; nf++) {
                    MMA16B(c[mf][nf], ah[mf], bh[nf]);
                    MMA16B(c[mf][nf], ah[mf], bl[nf]);
                    MMA16B(c[mf][nf], al[mf], bh[nf]);
                }
            }
        }
        __syncthreads();
    }

    #pragma unroll
    for (int mf = 0; mf < 4; mf++) {
        int r1 = n0 + warpM*64 + mf*16 + gr;
        #pragma unroll
        for (int nf = 0; nf < 4; nf++) {
            int gc = m0 + warpN*32 + nf*8 + lc*2;
            *(float2*)&g_G[(size_t)r1*MM + gc]       = make_float2(c[mf][nf][0], c[mf][nf][1]);
            *(float2*)&g_G[(size_t)(r1 + 8)*MM + gc] = make_float2(c[mf][nf][2], c[mf][nf][3]);
        }
    }
}

// ---------------- per-row stats with gumbel-bound candidate pruning ----------
// g = -log(-log(clamp(u))) is bounded in [-3.15, 16.13]. Any gumbel winner has
// dm >= vmax - 19.28; softmax terms below vmax-20 contribute < 2.1e-6 rel mass.
// So only candidates with dm > vmax-20 need exp/log processing. Unconditionally
// safe: worst case all 1024 are candidates.
__device__ __forceinline__ float gumbel_of(float u) {
    u = fminf(fmaxf(u, 1e-10f), 1.f - 1e-7f);
    return -__logf(-__logf(u));
}

// rational comparator: (e1/z1) > (e2/z2) for positive e,z; tie -> lower index
__device__ __forceinline__ bool rgt(float e1, float z1, int i1,
                                    float e2, float z2, int i2) {
    float a = e1*z2, b = e2*z1;
    return (a > b) || (a == b && i1 < i2);
}

#define RS_SMEMB (4096 + 32768 + 16384 + 32)

__global__ void __launch_bounds__(256) k_rowstats(const float* __restrict__ gum,
                                                  const float* __restrict__ emb,
                                                  float* __restrict__ out) {
    extern __shared__ char rsm[];
    float* sAcc = (float*)rsm;                                  // 1024
    float* sdvA = (float*)(rsm + 4096);                         // 8 x 1024
    unsigned short* sixA = (unsigned short*)(rsm + 4096 + 32768); // 8 x 1024
    int* ccnt = (int*)(rsm + 4096 + 32768 + 16384);             // 8

    int tid = threadIdx.x, wid = tid >> 5, lane = tid & 31;
    for (int i = tid; i < MM; i += 256) sAcc[i] = 0.f;
    __syncthreads();

    float* sdv = sdvA + wid*MM;
    unsigned short* six = sixA + wid*MM;

    float esq_r[8][4];
    #pragma unroll
    for (int ch = 0; ch < 8; ch++) {
        float4 v = *(const float4*)&g_esq[ch*128 + lane*4];
        esq_r[ch][0] = v.x; esq_r[ch][1] = v.y; esq_r[ch][2] = v.z; esq_r[ch][3] = v.w;
    }
    int nbase = blockIdx.x*16 + wid*2;

    #pragma unroll
    for (int r = 0; r < 2; r++) {
        int n = nbase + r;
        const float* Gr = g_G + (size_t)n*MM;
        const float* Ur = gum + (size_t)n*MM;
        if (lane == 0) ccnt[wid] = 0;
        __syncwarp();

        // pass 1: dm + value-max only
        float dm[8][4];
        float vmax = -3.4e38f;
        #pragma unroll
        for (int ch = 0; ch < 8; ch++) {
            float4 g4 = *(const float4*)&Gr[ch*128 + lane*4];
            dm[ch][0] = 2.f*g4.x - esq_r[ch][0];
            dm[ch][1] = 2.f*g4.y - esq_r[ch][1];
            dm[ch][2] = 2.f*g4.z - esq_r[ch][2];
            dm[ch][3] = 2.f*g4.w - esq_r[ch][3];
            vmax = fmaxf(vmax, fmaxf(fmaxf(dm[ch][0], dm[ch][1]), fmaxf(dm[ch][2], dm[ch][3])));
        }
        #pragma unroll
        for (int o = 16; o > 0; o >>= 1)
            vmax = fmaxf(vmax, __shfl_xor_sync(0xffffffffu, vmax, o));
        float T = vmax - 20.f;

        // compaction
        #pragma unroll
        for (int ch = 0; ch < 8; ch++)
            #pragma unroll
            for (int j = 0; j < 4; j++) {
                if (dm[ch][j] > T) {
                    int p = atomicAdd(&ccnt[wid], 1);
                    sdv[p] = dm[ch][j];
                    six[p] = (unsigned short)(ch*128 + lane*4 + j);
                }
            }
        __syncwarp();
        int C = ccnt[wid];

        // candidate pass: ssum, hard top2, gumbel top2 via (e, z) rationals
        float ssum = 0.f;
        float h1v = -3.4e38f, h2v = -3.4e38f; int h1i = 0x7fffffff, h2i = 0x7fffffff;
        float s1e = 0.f, s1z = 1.f; int s1i = 0x7fffffff;
        float s2e = 0.f, s2z = 1.f; int s2i = 0x7fffffff;
        for (int i = lane; i < C; i += 32) {
            float d = sdv[i];
            int m = six[i];
            float e = __expf(d - vmax);
            ssum += e;
            float u = fminf(fmaxf(Ur[m], 1e-10f), 1.f - 1e-7f);
            float z = -__logf(u);            // z > 0; score = e/z (monotone in dm+g)
            if (d > h1v || (d == h1v && m < h1i)) { h2v = h1v; h2i = h1i; h1v = d; h1i = m; }
            else if (d > h2v || (d == h2v && m < h2i)) { h2v = d; h2i = m; }
            if (rgt(e, z, m, s1e, s1z, s1i)) {
                s2e = s1e; s2z = s1z; s2i = s1i;
                s1e = e; s1z = z; s1i = m;
            } else if (rgt(e, z, m, s2e, s2z, s2i)) {
                s2e = e; s2z = z; s2i = m;
            }
        }
        // warp reduce ssum
        #pragma unroll
        for (int o = 16; o > 0; o >>= 1) ssum += __shfl_xor_sync(0xffffffffu, ssum, o);
        // warp merge hard top2
        #pragma unroll
        for (int o = 16; o > 0; o >>= 1) {
            float ov1 = __shfl_xor_sync(0xffffffffu, h1v, o);
            int   oi1 = __shfl_xor_sync(0xffffffffu, h1i, o);
            float ov2 = __shfl_xor_sync(0xffffffffu, h2v, o);
            int   oi2 = __shfl_xor_sync(0xffffffffu, h2i, o);
            if (ov1 > h1v || (ov1 == h1v && oi1 < h1i)) {
                float t1v = h1v; int t1i = h1i;
                h1v = ov1; h1i = oi1;
                if (t1v > ov2 || (t1v == ov2 && t1i < oi2)) { h2v = t1v; h2i = t1i; }
                else { h2v = ov2; h2i = oi2; }
            } else {
                if (ov1 > h2v || (ov1 == h2v && oi1 < h2i)) { h2v = ov1; h2i = oi1; }
            }
        }
        // warp merge gumbel top2 (rational comparator)
        #pragma unroll
        for (int o = 16; o > 0; o >>= 1) {
            float oe1 = __shfl_xor_sync(0xffffffffu, s1e, o);
            float oz1 = __shfl_xor_sync(0xffffffffu, s1z, o);
            int   oi1 = __shfl_xor_sync(0xffffffffu, s1i, o);
            float oe2 = __shfl_xor_sync(0xffffffffu, s2e, o);
            float oz2 = __shfl_xor_sync(0xffffffffu, s2z, o);
            int   oi2 = __shfl_xor_sync(0xffffffffu, s2i, o);
            if (rgt(oe1, oz1, oi1, s1e, s1z, s1i)) {
                if (rgt(s1e, s1z, s1i, oe2, oz2, oi2)) { s2e = s1e; s2z = s1z; s2i = s1i; }
                else { s2e = oe2; s2z = oz2; s2i = oi2; }
                s1e = oe1; s1z = oz1; s1i = oi1;
            } else {
                if (rgt(oe1, oz1, oi1, s2e, s2z, s2i)) { s2e = oe1; s2z = oz1; s2i = oi1; }
            }
        }
        if (h2i == 0x7fffffff) { h2v = h1v; h2i = h1i; }
        if (s2i == 0x7fffffff) { s2e = s1e; s2z = s1z; s2i = s1i; }

        // exact fp32 refinement of the 4 candidates (warp-cooperative dots)
        int cands[4] = {h1i, h2i, s1i, s2i};
        float ex[4];
        const float* curp = g_cur + (size_t)n*DD + lane*8;
        #pragma unroll
        for (int t = 0; t < 4; t++) {
            const float* Ep = emb + (size_t)cands[t]*DD + lane*8;
            float s = 0.f;
            #pragma unroll
            for (int j = 0; j < 8; j++) s += curp[j]*Ep[j];
            #pragma unroll
            for (int o = 16; o > 0; o >>= 1) s += __shfl_xor_sync(0xffffffffu, s, o);
            ex[t] = 2.f*s - g_esq[cands[t]];
        }

        // pAcc: second candidate sweep with known inv
        float inv = 1.f / ssum;
        for (int i = lane; i < C; i += 32) {
            float e = __expf(sdv[i] - vmax);
            atomicAdd(&sAcc[six[i]], e*inv);
        }

        if (lane == 0) {
            int kH = h1i; float vH = ex[0];
            if (ex[1] > vH || (ex[1] == vH && h2i < kH)) { kH = h2i; vH = ex[1]; }
            atomicAdd(&g_hist[kH], 1u);
            float sc0 = ex[2] + gumbel_of(Ur[s1i]);
            float sc1 = ex[3] + gumbel_of(Ur[s2i]);
            int kS = s1i;
            if (sc1 > sc0 || (sc1 == sc0 && s2i < s1i)) kS = s2i;
            g_idx[n] = kS;
            out[QSIZE + 2 + n] = (float)kS;
        }
        __syncwarp();
    }
    __syncthreads();
    for (int i = tid; i < MM; i += 256) atomicAdd(&g_avgp[i], sAcc[i]);
}

__global__ void k_finalize(float* __restrict__ out) {
    __shared__ float s1[MM];
    __shared__ float s2[MM];
    int m = threadIdx.x;
    float hp = (float)g_hist[m] * (1.f/(float)NN);
    float ap = g_avgp[m] * (1.f/(float)NN);
    s1[m] = -hp * log2f(hp + 1e-10f);
    s2[m] = -ap * log2f(ap + 1e-10f);
    __syncthreads();
    for (int s = 512; s > 0; s >>= 1) {
        if (m < s) { s1[m] += s1[m + s]; s2[m] += s2[m + s]; }
        __syncthreads();
    }
    if (m == 0) { out[QSIZE] = s1[0]; out[QSIZE + 1] = s2[0]; }
}

// ---------------- fuse2 (3xTF32, interleaved X, materialized W) --------------
#define F2_STG 3200
#define F2_SMEMB (64*130*4)

__global__ void __launch_bounds__(256) k_f2_tc(const float* __restrict__ a2p,
                                               float* __restrict__ out) {
    extern __shared__ float fs[];
    int tid = threadIdx.x, lane = tid & 31, warp = tid >> 5;
    int warpM = warp >> 2, warpN = warp & 3;
    int t0 = blockIdx.x*128, o0 = blockIdx.y*64, b = blockIdx.z;
    int ot0 = o0 >> 4;

    uint32_t sbase;
    asm("{ .reg .u64 t; cvta.to.shared.u64 t, %1; cvt.u32.u64 %0, t; }" : "=r"(sbase) : "l"(fs));

    auto issue = [&](int ic, int s) {
        uint32_t xd = sbase + (uint32_t)((s*F2_STG)*4);
        #pragma unroll
        for (int j = 0; j < 2; j++) {
            int idx = tid + j*256;
            int row = idx >> 6, q = idx & 63;
            const float2* sp = g_ctx2 + ((size_t)(b*DD + ic*8 + row))*TT + t0;
            asm volatile("cp.async.cg.shared.global [%0], [%1], 16;"
                :: "r"(xd + (uint32_t)((row*136 + q*2)*8)), "l"(sp + q*2));
        }
        if (tid < 128) {
            const float* wp = g_w2shh + ((size_t)ic*16 + ot0)*128;
            uint32_t wd = sbase + (uint32_t)((s*F2_STG + 2176)*4);
            asm volatile("cp.async.cg.shared.global [%0], [%1], 16;"
                :: "r"(wd + (uint32_t)(tid*16)), "l"(wp + tid*4));
        } else {
            int t2 = tid - 128;
            const float* wp = g_w2shl + ((size_t)ic*16 + ot0)*128;
            uint32_t wd = sbase + (uint32_t)((s*F2_STG + 2688)*4);
            asm volatile("cp.async.cg.shared.global [%0], [%1], 16;"
                :: "r"(wd + (uint32_t)(t2*16)), "l"(wp + t2*4));
        }
        asm volatile("cp.async.commit_group;");
    };

    float c[2][4][4] = {};
    issue(0, 0);
    issue(1, 1);

    for (int ic = 0; ic < 32; ic++) {
        int s = ic & 1;
        if (ic < 31) { asm volatile("cp.async.wait_group 1;"); }
        else         { asm volatile("cp.async.wait_group 0;"); }
        __syncthreads();
        const float2* X2 = (const float2*)(fs + s*F2_STG);
        const float* WH = fs + s*F2_STG + 2176;
        const float* WL = fs + s*F2_STG + 2688;
        int i0v = lane & 3, trow = lane >> 2;

        uint32_t ah[2][4], al[2][4];
        #pragma unroll
        for (int mf = 0; mf < 2; mf++) {
            float4 vh = *(const float4*)&WH[(warpM*2 + mf)*128 + lane*4];
            float4 vl = *(const float4*)&WL[(warpM*2 + mf)*128 + lane*4];
            ah[mf][0] = __float_as_uint(vh.x); ah[mf][1] = __float_as_uint(vh.y);
            ah[mf][2] = __float_as_uint(vh.z); ah[mf][3] = __float_as_uint(vh.w);
            al[mf][0] = __float_as_uint(vl.x); al[mf][1] = __float_as_uint(vl.y);
            al[mf][2] = __float_as_uint(vl.z); al[mf][3] = __float_as_uint(vl.w);
        }
        uint32_t bh[4][2], bl[4][2];
        #pragma unroll
        for (int nf = 0; nf < 4; nf++) {
            int toff = warpN*32 + nf*8 + trow;
            float2 v0 = X2[i0v*136 + toff];
            float2 v1 = X2[(i0v + 4)*136 + toff];
            bh[nf][0] = __float_as_uint(v0.x); bl[nf][0] = __float_as_uint(v0.y);
            bh[nf][1] = __float_as_uint(v1.x); bl[nf][1] = __float_as_uint(v1.y);
        }
        #pragma unroll
        for (int mf = 0; mf < 2; mf++) {
            #pragma unroll
            for (int nf = 0; nf < 4; nf++) {
                MMA8(c[mf][nf], ah[mf][0], ah[mf][1], ah[mf][2], ah[mf][3], bh[nf][0], bh[nf][1]);
                MMA8(c[mf][nf], ah[mf][0], ah[mf][1], ah[mf][2], ah[mf][3], bl[nf][0], bl[nf][1]);
                MMA8(c[mf][nf], al[mf][0], al[mf][1], al[mf][2], al[mf][3], bh[nf][0], bh[nf][1]);
            }
        }
        __syncthreads();
        if (ic + 2 < 32) issue(ic + 2, s);
    }

    #pragma unroll
    for (int mf = 0; mf < 2; mf++) {
        int r = warpM*32 + mf*16 + (lane >> 2);
        #pragma unroll
        for (int nf = 0; nf < 4; nf++) {
            int tg = warpN*32 + nf*8 + (lane & 3)*2;
            *(float2*)&fs[r*130 + tg]       = make_float2(c[mf][nf][0], c[mf][nf][1]);
            *(float2*)&fs[(r + 8)*130 + tg] = make_float2(c[mf][nf][2], c[mf][nf][3]);
        }
    }
    __syncthreads();
    float a2v = *a2p;
    int nl = tid >> 1, half = tid & 1;
    size_t n = (size_t)b*TT + t0 + nl;
    int mi = g_idx[n];
    const float* w2e = g_W2E + (size_t)mi*DD + o0 + half*32;
    float* op = out + n*DD + o0 + half*32;
    #pragma unroll
    for (int j = 0; j < 8; j++) {
        float4 w4 = *(const float4*)&w2e[j*4];
        float4 v;
        float u;
        u = fs[(half*32 + j*4 + 0)*130 + nl] + w4.x; v.x = (u >= 0.f) ? u : a2v*u;
        u = fs[(half*32 + j*4 + 1)*130 + nl] + w4.y; v.y = (u >= 0.f) ? u : a2v*u;
        u = fs[(half*32 + j*4 + 2)*130 + nl] + w4.z; v.z = (u >= 0.f) ? u : a2v*u;
        u = fs[(half*32 + j*4 + 3)*130 + nl] + w4.w; v.w = (u >= 0.f) ? u : a2v*u;
        *(float4*)&op[j*4] = v;
    }
}

// ---------------- launch -----------------------------------------------------
extern "C" void kernel_launch(void* const* d_in, const int* in_sizes, int n_in,
                              void* d_out, int out_size) {
    const float* x     = (const float*)d_in[0];
    const float* noise = (const float*)d_in[1];
    const float* gum   = (const float*)d_in[2];
    const int*   epo   = (const int*)  d_in[3];
    const float* emb   = (const float*)d_in[4];
    const float* wctx  = (const float*)d_in[5];
    const float* wf1   = (const float*)d_in[6];
    const float* a1    = (const float*)d_in[7];
    const float* wf2   = (const float*)d_in[8];
    const float* a2    = (const float*)d_in[9];
    float* out = (float*)d_out;

    cudaFuncSetAttribute(k_conv_tc, cudaFuncAttributeMaxDynamicSharedMemorySize, CV_SMEMB);
    cudaFuncSetAttribute(k_f1_tc, cudaFuncAttributeMaxDynamicSharedMemorySize, F1_SMEMB);
    cudaFuncSetAttribute(k_dist_b, cudaFuncAttributeMaxDynamicSharedMemorySize, DB_SMEMB);
    cudaFuncSetAttribute(k_f2_tc, cudaFuncAttributeMaxDynamicSharedMemorySize, F2_SMEMB);
    cudaFuncSetAttribute(k_rowstats, cudaFuncAttributeMaxDynamicSharedMemorySize, RS_SMEMB);

    dim3 tb32(32, 8);

    k_scale<<<BB, 256>>>(x, epo);                                   // 0
    k_noisy<<<dim3((LL + 31)/32, DD/32, BB), tb32>>>(x, noise);     // 1
    k_splitw<<<DD*DD*CTX/256, 256>>>(wctx);                         // 2
    k_conv_tc<<<dim3(TT/128, 4, BB), 256, CV_SMEMB>>>();            // 3 <- capture
    k_xt<<<dim3(TT/32, DD/32, BB), tb32>>>(x);
    k_splitw1<<<2*DD*DD/256, 256>>>(wf1);
    k_f1_tc<<<dim3(TT/128, DD/64, BB), 256, F1_SMEMB>>>(a1);
    k_transp<<<dim3(DD/32, MM/32), tb32>>>(emb, MM, DD, 0);         // ET
    k_transp<<<dim3(2*DD/32, DD/32), tb32>>>(wf2, DD, 2*DD, 1);     // w2T
    k_esq<<<MM/8, 256>>>(emb);
    k_zero<<<4, 256>>>();
    k_split_eb<<<MM*DD/256, 256>>>(emb);
    k_shufw2<<<DD*DD/256, 256>>>(wf2);
    k_gemm_w2e<<<dim3(MM/64, DD/64), 256>>>();
    k_dist_b<<<dim3(NN/128, MM/128), 256, DB_SMEMB>>>();
    k_rowstats<<<NN/16, 256, RS_SMEMB>>>(gum, emb, out);
    k_finalize<<<1, MM>>>(out);
    k_f2_tc<<<dim3(TT/128, DD/64, BB), 256, F2_SMEMB>>>(a2, out);
}

// round 15
// speedup vs baseline: 1.0195x; 1.0195x over previous
#include <cuda_runtime.h>
#include <cuda_bf16.h>
#include <math.h>
#include <stdint.h>

#define BB 8
#define TT 4096
#define DD 256
#define MM 1024
#define CTX 7
#define LL (TT - 1 + CTX)      /* 4102 */
#define LLP 4104               /* padded stride */
#define NN (BB*TT)             /* 32768 */
#define QSIZE (NN*DD)          /* 8388608 */

// ---------------- scratch ----------------------------------------------------
__device__ __align__(16) float2 g_xt2[BB*DD*TT];        // x^T as (tf32hi, lo)
__device__ __align__(16) float2 g_noisy2[BB*DD*LLP];    // noisy ctx-in (hi, lo)
__device__ __align__(16) float2 g_ctx2[BB*DD*TT];       // conv out (hi, lo)
__device__ __align__(16) float g_wch[DD*DD*CTX];        // w_ctx hi, A-frag shuffled
__device__ __align__(16) float g_wcl[DD*DD*CTX];
__device__ __align__(16) float g_w1shh[2*DD*DD];
__device__ __align__(16) float g_w1shl[2*DD*DD];
__device__ __align__(16) float g_w2shh[DD*DD];
__device__ __align__(16) float g_w2shl[DD*DD];
__device__ __align__(16) float g_cur[(size_t)NN*DD];    // fuse1 out, exact fp32
__device__ __align__(16) __nv_bfloat16 g_cur_bh[(size_t)NN*DD];
__device__ __align__(16) __nv_bfloat16 g_cur_bl[(size_t)NN*DD];
__device__ __align__(16) __nv_bfloat16 g_E_bh[MM*DD];
__device__ __align__(16) __nv_bfloat16 g_E_bl[MM*DD];
__device__ __align__(16) float g_G[(size_t)NN*MM];
__device__ __align__(16) float g_ET[DD*MM];
__device__ __align__(16) float g_w2T[2*DD*DD];
__device__ __align__(16) float g_W2E[MM*DD];
__device__ __align__(16) float g_esq[MM];
__device__ float g_scale[BB];
__device__ int   g_idx[NN];
__device__ unsigned int g_hist[MM];
__device__ float g_avgp[MM];

__device__ __forceinline__ float tf32_hi(float v) {
    uint32_t b;
    asm("cvt.rna.tf32.f32 %0, %1;" : "=r"(b) : "f"(v));
    return __uint_as_float(b);
}

#define MMA8(d, a0,a1,a2,a3, b0,b1) \
    asm volatile("mma.sync.aligned.m16n8k8.row.col.f32.tf32.tf32.f32 " \
        "{%0,%1,%2,%3}, {%4,%5,%6,%7}, {%8,%9}, {%0,%1,%2,%3};" \
        : "+f"((d)[0]), "+f"((d)[1]), "+f"((d)[2]), "+f"((d)[3]) \
        : "r"(a0), "r"(a1), "r"(a2), "r"(a3), "r"(b0), "r"(b1))

#define MMA16B(d, a, b) \
    asm volatile("mma.sync.aligned.m16n8k16.row.col.f32.bf16.bf16.f32 " \
        "{%0,%1,%2,%3}, {%4,%5,%6,%7}, {%8,%9}, {%0,%1,%2,%3};" \
        : "+f"((d)[0]), "+f"((d)[1]), "+f"((d)[2]), "+f"((d)[3]) \
        : "r"((a)[0]), "r"((a)[1]), "r"((a)[2]), "r"((a)[3]), "r"((b)[0]), "r"((b)[1]))

// ---------------- fused prep kernels -----------------------------------------
// block = one E row: bf16 split + esq reduce; blocks 0..3 also zero hist/avgp
__global__ void k_prep_e(const float* __restrict__ E) {
    __shared__ float sm[8];
    int m = blockIdx.x, tid = threadIdx.x;
    float v = E[(size_t)m*DD + tid];
    __nv_bfloat16 h = __float2bfloat16(v);
    g_E_bh[(size_t)m*DD + tid] = h;
    g_E_bl[(size_t)m*DD + tid] = __float2bfloat16(v - __bfloat162float(h));
    float s = v*v;
    #pragma unroll
    for (int o = 16; o > 0; o >>= 1) s += __shfl_down_sync(0xffffffffu, s, o);
    if ((tid & 31) == 0) sm[tid >> 5] = s;
    __syncthreads();
    if (tid == 0) {
        float t = 0.f;
        #pragma unroll
        for (int w = 0; w < 8; w++) t += sm[w];
        g_esq[m] = t;
    }
    if (m < 4) { g_hist[m*256 + tid] = 0u; g_avgp[m*256 + tid] = 0.f; }
}

// fused weight shuffles/splits: blocks [0,1792) w_ctx, [1792,2304) w_f1, [2304,2560) w_f2b
__global__ void k_prep_w(const float* __restrict__ wctx,
                         const float* __restrict__ wf1,
                         const float* __restrict__ wf2) {
    int b = blockIdx.x, tid = threadIdx.x;
    if (b < 1792) {
        int idx = b*256 + tid;
        int o = idx / (DD*CTX);
        int rem = idx - o*(DD*CTX);
        int i = rem / CTX, kk = rem - i*CTX;
        float v = wctx[idx];
        float h = tf32_hi(v);
        int ic = i >> 3, il = i & 7;
        int otile = o >> 4, oloc = o & 15;
        int lane = (oloc & 7)*4 + (il & 3);
        int reg = (oloc >> 3) + 2*(il >> 2);
        int d = ((ic*7 + kk)*16 + otile)*128 + lane*4 + reg;
        g_wch[d] = h;
        g_wcl[d] = tf32_hi(v - h);
    } else if (b < 2304) {
        int idx = (b - 1792)*256 + tid;
        int o = idx >> 9, k = idx & 511;
        float v = wf1[idx];
        float h = tf32_hi(v);
        int ks = k >> 3, il = k & 7;
        int otile = o >> 4, oloc = o & 15;
        int lane = (oloc & 7)*4 + (il & 3);
        int reg = (oloc >> 3) + 2*(il >> 2);
        int d = (ks*16 + otile)*128 + lane*4 + reg;
        g_w1shh[d] = h;
        g_w1shl[d] = tf32_hi(v - h);
    } else {
        int idx = (b - 2304)*256 + tid;
        int o = idx >> 8, k = idx & 255;
        int ic = k >> 3, il = k & 7;
        int otile = o >> 4, oloc = o & 15;
        int lane = (oloc & 7)*4 + (il & 3);
        int reg = (oloc >> 3) + 2*(il >> 2);
        float v = wf2[o*2*DD + DD + k];
        float h = tf32_hi(v);
        int d = (ic*16 + otile)*128 + lane*4 + reg;
        g_w2shh[d] = h;
        g_w2shl[d] = tf32_hi(v - h);
    }
}

__global__ void k_transp(const float* __restrict__ src, int rows, int cols, int which) {
    __shared__ float s[32][33];
    float* dst = (which == 0) ? g_ET : g_w2T;
    int c0 = blockIdx.x*32, r0 = blockIdx.y*32;
    int tx = threadIdx.x, ty = threadIdx.y;
    #pragma unroll
    for (int j = 0; j < 4; j++) {
        int r = r0 + ty + j*8, c = c0 + tx;
        s[ty + j*8][tx] = (r < rows && c < cols) ? src[(size_t)r*cols + c] : 0.f;
    }
    __syncthreads();
    #pragma unroll
    for (int j = 0; j < 4; j++) {
        int c = c0 + ty + j*8, r = r0 + tx;
        if (c < cols && r < rows) dst[(size_t)c*rows + r] = s[tx][ty + j*8];
    }
}

__global__ void k_scale(const float* __restrict__ x, const int* __restrict__ epo_p) {
    int b = blockIdx.x;
    const float* xb = x + (size_t)b*TT*DD;
    float s = 0.f;
    int tot = (TT-1)*DD;
    for (int i = threadIdx.x; i < tot; i += blockDim.x) { float v = xb[i]; s += v*v; }
    __shared__ float sm[8];
    #pragma unroll
    for (int o = 16; o > 0; o >>= 1) s += __shfl_down_sync(0xffffffffu, s, o);
    if ((threadIdx.x & 31) == 0) sm[threadIdx.x >> 5] = s;
    __syncthreads();
    if (threadIdx.x == 0) {
        float t = 0.f;
        for (int w = 0; w < 8; w++) t += sm[w];
        int iv = epo_p[0];
        float ef = (iv >= 0 && iv < 100000) ? (float)iv : __int_as_float(iv);
        float sc = sqrtf(t / (float)(DD*LL));
        g_scale[b] = 0.5f * sc * exp2f(-ef * 0.1f);
    }
}

// x -> xt2 (hi,lo) [b][d][t]
__global__ void k_xt(const float* __restrict__ x) {
    __shared__ float s[32][33];
    int b = blockIdx.z, t0 = blockIdx.x*32, d0 = blockIdx.y*32;
    int tx = threadIdx.x, ty = threadIdx.y;
    #pragma unroll
    for (int j = 0; j < 4; j++) {
        int t = t0 + ty + j*8;
        s[ty + j*8][tx] = x[((size_t)b*TT + t)*DD + d0 + tx];
    }
    __syncthreads();
    #pragma unroll
    for (int j = 0; j < 4; j++) {
        int d = d0 + ty + j*8;
        float v = s[tx][ty + j*8];
        float h = tf32_hi(v);
        g_xt2[((size_t)b*DD + d)*TT + t0 + tx] = make_float2(h, tf32_hi(v - h));
    }
}

__global__ void k_noisy(const float* __restrict__ x, const float* __restrict__ noise) {
    __shared__ float s[32][33];
    int b = blockIdx.z, l0 = blockIdx.x*32, i0 = blockIdx.y*32;
    int tx = threadIdx.x, ty = threadIdx.y;
    float coef = g_scale[b];
    #pragma unroll
    for (int j = 0; j < 4; j++) {
        int row = ty + j*8;
        int t = l0 + row - CTX;
        float v = (t >= 0 && t < TT-1) ? x[((size_t)b*TT + t)*DD + i0 + tx] : 0.f;
        s[row][tx] = v;
    }
    __syncthreads();
    #pragma unroll
    for (int j = 0; j < 4; j++) {
        int i = i0 + ty + j*8, l = l0 + tx;
        if (l < LL) {
            float v = s[tx][ty + j*8] + coef * noise[((size_t)b*DD + i)*LL + l];
            float h = tf32_hi(v);
            g_noisy2[((size_t)b*DD + i)*LLP + l] = make_float2(h, tf32_hi(v - h));
        }
    }
}

// ---------------- conv (3xTF32, interleaved X, materialized W) ---------------
#define CV_STG 9344
#define CV_SMEMB (2*CV_STG*4)

__global__ void __launch_bounds__(256, 2) k_conv_tc() {
    extern __shared__ float cs[];
    int tid = threadIdx.x, lane = tid & 31, warp = tid >> 5;
    int warpM = warp >> 2, warpN = warp & 3;
    int t0 = blockIdx.x*128, o0 = blockIdx.y*64, b = blockIdx.z;
    int ot0 = o0 >> 4;

    uint32_t sbase;
    asm("{ .reg .u64 t; cvta.to.shared.u64 t, %1; cvt.u32.u64 %0, t; }" : "=r"(sbase) : "l"(cs));

    auto issue = [&](int ic, int s) {
        const float2* xp = g_noisy2 + ((size_t)(b*DD + ic*8))*LLP + t0;
        uint32_t xd = sbase + (uint32_t)((s*CV_STG)*4);
        for (int idx = tid; idx < 544; idx += 256) {
            int row = idx / 68, q = idx - row*68;
            asm volatile("cp.async.cg.shared.global [%0], [%1], 16;"
                :: "r"(xd + (uint32_t)((row*136 + q*2)*8)), "l"(xp + (size_t)row*LLP + q*2));
        }
        const float* wh = g_wch + ((size_t)(ic*7)*16 + ot0)*128;
        const float* wl = g_wcl + ((size_t)(ic*7)*16 + ot0)*128;
        uint32_t wdh = sbase + (uint32_t)((s*CV_STG + 2176)*4);
        uint32_t wdl = wdh + 3584*4;
        for (int idx = tid; idx < 896; idx += 256) {
            int kk = idx >> 7, q = idx & 127;
            asm volatile("cp.async.cg.shared.global [%0], [%1], 16;"
                :: "r"(wdh + (uint32_t)((kk*512 + q*4)*4)), "l"(wh + kk*2048 + q*4));
            asm volatile("cp.async.cg.shared.global [%0], [%1], 16;"
                :: "r"(wdl + (uint32_t)((kk*512 + q*4)*4)), "l"(wl + kk*2048 + q*4));
        }
        asm volatile("cp.async.commit_group;");
    };

    float c[2][4][4] = {};
    issue(0, 0);
    issue(1, 1);

    for (int ic = 0; ic < 32; ic++) {
        int s = ic & 1;
        if (ic < 31) { asm volatile("cp.async.wait_group 1;"); }
        else         { asm volatile("cp.async.wait_group 0;"); }
        __syncthreads();
        const float2* X2 = (const float2*)(cs + s*CV_STG);
        const float* WH = cs + s*CV_STG + 2176;
        const float* WL = cs + s*CV_STG + 5760;
        int i0v = lane & 3, trow = lane >> 2;

        #pragma unroll
        for (int kk = 0; kk < 7; kk++) {
            uint32_t ah[2][4], al[2][4];
            #pragma unroll
            for (int mf = 0; mf < 2; mf++) {
                float4 vh = *(const float4*)&WH[kk*512 + (warpM*2 + mf)*128 + lane*4];
                float4 vl = *(const float4*)&WL[kk*512 + (warpM*2 + mf)*128 + lane*4];
                ah[mf][0] = __float_as_uint(vh.x); ah[mf][1] = __float_as_uint(vh.y);
                ah[mf][2] = __float_as_uint(vh.z); ah[mf][3] = __float_as_uint(vh.w);
                al[mf][0] = __float_as_uint(vl.x); al[mf][1] = __float_as_uint(vl.y);
                al[mf][2] = __float_as_uint(vl.z); al[mf][3] = __float_as_uint(vl.w);
            }
            uint32_t bh[4][2], bl[4][2];
            #pragma unroll
            for (int nf = 0; nf < 4; nf++) {
                int toff = warpN*32 + nf*8 + trow + kk;
                float2 v0 = X2[i0v*136 + toff];
                float2 v1 = X2[(i0v + 4)*136 + toff];
                bh[nf][0] = __float_as_uint(v0.x); bl[nf][0] = __float_as_uint(v0.y);
                bh[nf][1] = __float_as_uint(v1.x); bl[nf][1] = __float_as_uint(v1.y);
            }
            #pragma unroll
            for (int mf = 0; mf < 2; mf++) {
                #pragma unroll
                for (int nf = 0; nf < 4; nf++) {
                    MMA8(c[mf][nf], ah[mf][0], ah[mf][1], ah[mf][2], ah[mf][3], bh[nf][0], bh[nf][1]);
                    MMA8(c[mf][nf], ah[mf][0], ah[mf][1], ah[mf][2], ah[mf][3], bl[nf][0], bl[nf][1]);
                    MMA8(c[mf][nf], al[mf][0], al[mf][1], al[mf][2], al[mf][3], bh[nf][0], bh[nf][1]);
                }
            }
        }
        __syncthreads();
        if (ic + 2 < 32) issue(ic + 2, s);
    }

    #pragma unroll
    for (int mf = 0; mf < 2; mf++) {
        int r = o0 + warpM*32 + mf*16 + (lane >> 2);
        #pragma unroll
        for (int nf = 0; nf < 4; nf++) {
            int tg = t0 + warpN*32 + nf*8 + (lane & 3)*2;
            float v0 = c[mf][nf][0], v1 = c[mf][nf][1];
            float v2 = c[mf][nf][2], v3 = c[mf][nf][3];
            float h0 = tf32_hi(v0), h1 = tf32_hi(v1), h2 = tf32_hi(v2), h3 = tf32_hi(v3);
            size_t o1 = ((size_t)b*DD + r)*TT + tg;
            size_t o2 = ((size_t)b*DD + r + 8)*TT + tg;
            *(float4*)&g_ctx2[o1] = make_float4(h0, tf32_hi(v0 - h0), h1, tf32_hi(v1 - h1));
            *(float4*)&g_ctx2[o2] = make_float4(h2, tf32_hi(v2 - h2), h3, tf32_hi(v3 - h3));
        }
    }
}

// ---------------- fuse1 on tensor cores (3xTF32, interleaved X) --------------
#define F1_STG 6400
#define F1_SMEMB (2*F1_STG*4)

__global__ void __launch_bounds__(256, 2) k_f1_tc(const float* __restrict__ a1p) {
    extern __shared__ float fs[];
    int tid = threadIdx.x, lane = tid & 31, warp = tid >> 5;
    int warpM = warp >> 2, warpN = warp & 3;
    int t0 = blockIdx.x*128, o0 = blockIdx.y*64, b = blockIdx.z;
    int ot0 = o0 >> 4;

    uint32_t sbase;
    asm("{ .reg .u64 t; cvta.to.shared.u64 t, %1; cvt.u32.u64 %0, t; }" : "=r"(sbase) : "l"(fs));

    auto issue = [&](int cchunk, int s) {
        uint32_t xd = sbase + (uint32_t)((s*F1_STG)*4);
        #pragma unroll
        for (int j = 0; j < 4; j++) {
            int idx = tid + j*256;
            int row = idx >> 6, q = idx & 63;
            int d = cchunk*16 + row;
            const float2* sp = (d < DD) ? (g_xt2 + ((size_t)b*DD + d)*TT + t0)
                                        : (g_ctx2 + ((size_t)b*DD + d - DD)*TT + t0);
            asm volatile("cp.async.cg.shared.global [%0], [%1], 16;"
                :: "r"(xd + (uint32_t)((row*136 + q*2)*8)), "l"(sp + q*2));
        }
        const float* wh = g_w1shh + ((size_t)(cchunk*2)*16 + ot0)*128;
        const float* wl = g_w1shl + ((size_t)(cchunk*2)*16 + ot0)*128;
        uint32_t wdh = sbase + (uint32_t)((s*F1_STG + 4352)*4);
        uint32_t wdl = wdh + 1024*4;
        {
            int sl8 = tid >> 7, q = tid & 127;
            asm volatile("cp.async.cg.shared.global [%0], [%1], 16;"
                :: "r"(wdh + (uint32_t)(tid*16)), "l"(wh + sl8*2048 + q*4));
            asm volatile("cp.async.cg.shared.global [%0], [%1], 16;"
                :: "r"(wdl + (uint32_t)(tid*16)), "l"(wl + sl8*2048 + q*4));
        }
        asm volatile("cp.async.commit_group;");
    };

    float c[2][4][4] = {};
    issue(0, 0);
    issue(1, 1);

    for (int cc = 0; cc < 32; cc++) {
        int s = cc & 1;
        if (cc < 31) { asm volatile("cp.async.wait_group 1;"); }
        else         { asm volatile("cp.async.wait_group 0;"); }
        __syncthreads();
        const float2* X2 = (const float2*)(fs + s*F1_STG);
        const float* WH = fs + s*F1_STG + 4352;
        const float* WL = fs + s*F1_STG + 5376;
        int i0v = lane & 3, trow = lane >> 2;

        #pragma unroll
        for (int sl8 = 0; sl8 < 2; sl8++) {
            uint32_t ah[2][4], al[2][4];
            #pragma unroll
            for (int mf = 0; mf < 2; mf++) {
                float4 vh = *(const float4*)&WH[sl8*512 + (warpM*2 + mf)*128 + lane*4];
                float4 vl = *(const float4*)&WL[sl8*512 + (warpM*2 + mf)*128 + lane*4];
                ah[mf][0] = __float_as_uint(vh.x); ah[mf][1] = __float_as_uint(vh.y);
                ah[mf][2] = __float_as_uint(vh.z); ah[mf][3] = __float_as_uint(vh.w);
                al[mf][0] = __float_as_uint(vl.x); al[mf][1] = __float_as_uint(vl.y);
                al[mf][2] = __float_as_uint(vl.z); al[mf][3] = __float_as_uint(vl.w);
            }
            uint32_t bh[4][2], bl[4][2];
            #pragma unroll
            for (int nf = 0; nf < 4; nf++) {
                int toff = warpN*32 + nf*8 + trow;
                int rbase = sl8*8 + i0v;
                float2 v0 = X2[rbase*136 + toff];
                float2 v1 = X2[(rbase + 4)*136 + toff];
                bh[nf][0] = __float_as_uint(v0.x); bl[nf][0] = __float_as_uint(v0.y);
                bh[nf][1] = __float_as_uint(v1.x); bl[nf][1] = __float_as_uint(v1.y);
            }
            #pragma unroll
            for (int mf = 0; mf < 2; mf++) {
                #pragma unroll
                for (int nf = 0; nf < 4; nf++) {
                    MMA8(c[mf][nf], ah[mf][0], ah[mf][1], ah[mf][2], ah[mf][3], bh[nf][0], bh[nf][1]);
                    MMA8(c[mf][nf], ah[mf][0], ah[mf][1], ah[mf][2], ah[mf][3], bl[nf][0], bl[nf][1]);
                    MMA8(c[mf][nf], al[mf][0], al[mf][1], al[mf][2], al[mf][3], bh[nf][0], bh[nf][1]);
                }
            }
        }
        __syncthreads();
        if (cc + 2 < 32) issue(cc + 2, s);
    }

    float a1 = *a1p;
    #pragma unroll
    for (int mf = 0; mf < 2; mf++) {
        int r = warpM*32 + mf*16 + (lane >> 2);
        #pragma unroll
        for (int nf = 0; nf < 4; nf++) {
            int tg = warpN*32 + nf*8 + (lane & 3)*2;
            float v0 = c[mf][nf][0]; v0 = (v0 >= 0.f) ? v0 : a1*v0;
            float v1 = c[mf][nf][1]; v1 = (v1 >= 0.f) ? v1 : a1*v1;
            float v2 = c[mf][nf][2]; v2 = (v2 >= 0.f) ? v2 : a1*v2;
            float v3 = c[mf][nf][3]; v3 = (v3 >= 0.f) ? v3 : a1*v3;
            *(float2*)&fs[r*130 + tg]       = make_float2(v0, v1);
            *(float2*)&fs[(r + 8)*130 + tg] = make_float2(v2, v3);
        }
    }
    __syncthreads();
    int nl = tid >> 1, half = tid & 1;
    size_t n = (size_t)b*TT + t0 + nl;
    float* cp = g_cur + n*DD + o0 + half*32;
    __nv_bfloat16* bhp = g_cur_bh + n*DD + o0 + half*32;
    __nv_bfloat16* blp = g_cur_bl + n*DD + o0 + half*32;
    #pragma unroll
    for (int j = 0; j < 8; j++) {
        float4 v;
        v.x = fs[(half*32 + j*4 + 0)*130 + nl];
        v.y = fs[(half*32 + j*4 + 1)*130 + nl];
        v.z = fs[(half*32 + j*4 + 2)*130 + nl];
        v.w = fs[(half*32 + j*4 + 3)*130 + nl];
        *(float4*)&cp[j*4] = v;
        float vv[4] = {v.x, v.y, v.z, v.w};
        __nv_bfloat16 bh4[4], bl4[4];
        #pragma unroll
        for (int q = 0; q < 4; q++) {
            bh4[q] = __float2bfloat16(vv[q]);
            bl4[q] = __float2bfloat16(vv[q] - __bfloat162float(bh4[q]));
        }
        *(uint2*)&bhp[j*4] = *(uint2*)bh4;
        *(uint2*)&blp[j*4] = *(uint2*)bl4;
    }
}

// ---------------- W2E GEMM (small) -------------------------------------------
__global__ void __launch_bounds__(256) k_gemm_w2e() {
    __shared__ float sA[16][68];
    __shared__ float sB[16][68];
    int i0 = blockIdx.x*64, j0 = blockIdx.y*64;
    int tid = threadIdx.x;
    int tx = tid & 15, ty = tid >> 4;
    int kl = tid >> 4, nl4 = (tid & 15)*4;
    float acc[4][4] = {};
    for (int kc = 0; kc < DD; kc += 16) {
        *(float4*)&sA[kl][nl4] = *(const float4*)(g_ET  + (size_t)(kc + kl)*MM + i0 + nl4);
        *(float4*)&sB[kl][nl4] = *(const float4*)(g_w2T + (size_t)(kc + kl)*DD + j0 + nl4);
        __syncthreads();
        #pragma unroll
        for (int k = 0; k < 16; k++) {
            float4 av = *(const float4*)&sA[k][4*tx];
            float4 bv = *(const float4*)&sB[k][4*ty];
            float ar[4] = {av.x, av.y, av.z, av.w};
            float br[4] = {bv.x, bv.y, bv.z, bv.w};
            #pragma unroll
            for (int a = 0; a < 4; a++)
                #pragma unroll
                for (int cc = 0; cc < 4; cc++)
                    acc[a][cc] += br[a] * ar[cc];
        }
        __syncthreads();
    }
    #pragma unroll
    for (int cc = 0; cc < 4; cc++) {
        int i = i0 + 4*tx + cc;
        float4 v = make_float4(acc[0][cc], acc[1][cc], acc[2][cc], acc[3][cc]);
        *(float4*)&g_W2E[(size_t)i*DD + j0 + 4*ty] = v;
    }
}

// ---------------- dist GEMM via mma.sync bf16 (3xBF16, k16) ------------------
#define DB_ROWW 20
#define DB_ARRW (128*DB_ROWW)
#define DB_STGW (4*DB_ARRW)
#define DB_SMEMB (2*DB_STGW*4)

__global__ void __launch_bounds__(256, 2) k_dist_b() {
    extern __shared__ uint32_t dsm[];
    int tid = threadIdx.x, lane = tid & 31, warp = tid >> 5;
    int warpM = warp >> 2, warpN = warp & 3;
    int n0 = blockIdx.x*128, m0 = blockIdx.y*128;

    uint32_t sbase;
    asm("{ .reg .u64 t; cvta.to.shared.u64 t, %1; cvt.u32.u64 %0, t; }" : "=r"(sbase) : "l"(dsm));

    const __nv_bfloat16* srcs[4] = {
        g_cur_bh + (size_t)n0*DD, g_cur_bl + (size_t)n0*DD,
        g_E_bh   + (size_t)m0*DD, g_E_bl   + (size_t)m0*DD };

    auto issue = [&](int kc, int s) {
        #pragma unroll
        for (int a = 0; a < 4; a++) {
            uint32_t dstb = sbase + (uint32_t)((s*DB_STGW + a*DB_ARRW)*4);
            #pragma unroll
            for (int j = 0; j < 2; j++) {
                int cid = tid + j*256;
                int row = cid >> 2, q = cid & 3;
                uint32_t dst = dstb + (uint32_t)(row*80 + q*16);
                const __nv_bfloat16* src = srcs[a] + (size_t)row*DD + kc + q*8;
                asm volatile("cp.async.cg.shared.global [%0], [%1], 16;"
                             :: "r"(dst), "l"(src));
            }
        }
        asm volatile("cp.async.commit_group;");
    };

    float c[4][4][4] = {};
    issue(0, 0);

    int gr = lane >> 2, lc = lane & 3;
    for (int it = 0; it < 8; it++) {
        int s = it & 1;
        if (it + 1 < 8) issue((it + 1)*32, s ^ 1);
        if (it + 1 < 8) { asm volatile("cp.async.wait_group 1;"); }
        else            { asm volatile("cp.async.wait_group 0;"); }
        __syncthreads();

        const uint32_t* sAh = dsm + s*DB_STGW;
        const uint32_t* sAl = sAh + DB_ARRW;
        const uint32_t* sBh = sAh + 2*DB_ARRW;
        const uint32_t* sBl = sAh + 3*DB_ARRW;

        #pragma unroll
        for (int ks = 0; ks < 2; ks++) {
            int wb = ks*8 + lc;
            uint32_t ah[4][4], al[4][4], bh[4][2], bl[4][2];
            #pragma unroll
            for (int mf = 0; mf < 4; mf++) {
                int r1 = (warpM*64 + mf*16 + gr)*DB_ROWW, r2 = r1 + 8*DB_ROWW;
                ah[mf][0] = sAh[r1 + wb];     ah[mf][1] = sAh[r2 + wb];
                ah[mf][2] = sAh[r1 + wb + 4]; ah[mf][3] = sAh[r2 + wb + 4];
                al[mf][0] = sAl[r1 + wb];     al[mf][1] = sAl[r2 + wb];
                al[mf][2] = sAl[r1 + wb + 4]; al[mf][3] = sAl[r2 + wb + 4];
            }
            #pragma unroll
            for (int nf = 0; nf < 4; nf++) {
                int rn = (warpN*32 + nf*8 + gr)*DB_ROWW;
                bh[nf][0] = sBh[rn + wb]; bh[nf][1] = sBh[rn + wb + 4];
                bl[nf][0] = sBl[rn + wb]; bl[nf][1] = sBl[rn + wb + 4];
            }
            #pragma unroll
            for (int mf = 0; mf < 4; mf++) {
                #pragma unroll
                for (int nf = 0; nf < 4; nf++) {
                    MMA16B(c[mf][nf], ah[mf], bh[nf]);
                    MMA16B(c[mf][nf], ah[mf], bl[nf]);
                    MMA16B(c[mf][nf], al[mf], bh[nf]);
                }
            }
        }
        __syncthreads();
    }

    #pragma unroll
    for (int mf = 0; mf < 4; mf++) {
        int r1 = n0 + warpM*64 + mf*16 + gr;
        #pragma unroll
        for (int nf = 0; nf < 4; nf++) {
            int gc = m0 + warpN*32 + nf*8 + lc*2;
            *(float2*)&g_G[(size_t)r1*MM + gc]       = make_float2(c[mf][nf][0], c[mf][nf][1]);
            *(float2*)&g_G[(size_t)(r1 + 8)*MM + gc] = make_float2(c[mf][nf][2], c[mf][nf][3]);
        }
    }
}

// ---------------- per-row stats (rational gumbel; 1 log + shared exp/elem) ---
__device__ __forceinline__ float gumbel_of(float u) {
    u = fminf(fmaxf(u, 1e-10f), 1.f - 1e-7f);
    return -__logf(-__logf(u));
}

// rational comparator: (e1/z1) > (e2/z2) for e>=0, z>0; tie -> lower index
__device__ __forceinline__ bool rgt(float e1, float z1, int i1,
                                    float e2, float z2, int i2) {
    float a = e1*z2, b = e2*z1;
    return (a > b) || (a == b && i1 < i2);
}

__global__ void __launch_bounds__(256) k_rowstats(const float* __restrict__ gum,
                                                  const float* __restrict__ emb,
                                                  float* __restrict__ out) {
    __shared__ float sAcc[MM];
    int tid = threadIdx.x, wid = tid >> 5, lane = tid & 31;
    for (int i = tid; i < MM; i += 256) sAcc[i] = 0.f;
    __syncthreads();

    float esq_r[8][4];
    #pragma unroll
    for (int ch = 0; ch < 8; ch++) {
        float4 v = *(const float4*)&g_esq[ch*128 + lane*4];
        esq_r[ch][0] = v.x; esq_r[ch][1] = v.y; esq_r[ch][2] = v.z; esq_r[ch][3] = v.w;
    }
    float pAcc[8][4] = {};
    int nbase = blockIdx.x*16 + wid*2;

    #pragma unroll
    for (int r = 0; r < 2; r++) {
        int n = nbase + r;
        const float* Gr = g_G + (size_t)n*MM;
        const float* Ur = gum + (size_t)n*MM;
        float dm[8][4];
        // sweep 1: dm + hard top2 (h1v doubles as vmax)
        float h1v = -3.4e38f, h2v = -3.4e38f; int h1i = 0x7fffffff, h2i = 0x7fffffff;
        #pragma unroll
        for (int ch = 0; ch < 8; ch++) {
            float4 g4 = *(const float4*)&Gr[ch*128 + lane*4];
            float gg[4] = {g4.x, g4.y, g4.z, g4.w};
            #pragma unroll
            for (int j = 0; j < 4; j++) {
                int m = ch*128 + lane*4 + j;
                float d = 2.f*gg[j] - esq_r[ch][j];
                dm[ch][j] = d;
                if (d > h1v || (d == h1v && m < h1i)) { h2v = h1v; h2i = h1i; h1v = d; h1i = m; }
                else if (d > h2v || (d == h2v && m < h2i)) { h2v = d; h2i = m; }
            }
        }
        // warp merge hard top2 -> h1v is the global row max (vmax)
        #pragma unroll
        for (int o = 16; o > 0; o >>= 1) {
            float ov1 = __shfl_xor_sync(0xffffffffu, h1v, o);
            int   oi1 = __shfl_xor_sync(0xffffffffu, h1i, o);
            float ov2 = __shfl_xor_sync(0xffffffffu, h2v, o);
            int   oi2 = __shfl_xor_sync(0xffffffffu, h2i, o);
            if (ov1 > h1v || (ov1 == h1v && oi1 < h1i)) {
                float t1v = h1v; int t1i = h1i;
                h1v = ov1; h1i = oi1;
                if (t1v > ov2 || (t1v == ov2 && t1i < oi2)) { h2v = t1v; h2i = t1i; }
                else { h2v = ov2; h2i = oi2; }
            } else {
                if (ov1 > h2v || (ov1 == h2v && oi1 < h2i)) { h2v = ov1; h2i = oi1; }
            }
        }

        // sweep 2 (registers + u reload): exp for softmax + rational gumbel top2
        float ssum = 0.f;
        float s1e = 0.f, s1z = 1.f; int s1i = 0x7fffffff;
        float s2e = 0.f, s2z = 1.f; int s2i = 0x7fffffff;
        #pragma unroll
        for (int ch = 0; ch < 8; ch++) {
            float4 u4 = *(const float4*)&Ur[ch*128 + lane*4];
            float uu[4] = {u4.x, u4.y, u4.z, u4.w};
            #pragma unroll
            for (int j = 0; j < 4; j++) {
                int m = ch*128 + lane*4 + j;
                float e = __expf(dm[ch][j] - h1v);
                dm[ch][j] = e;       // reuse for pAcc pass
                ssum += e;
                float u = fminf(fmaxf(uu[j], 1e-10f), 1.f - 1e-7f);
                float z = -__logf(u);        // z > 0; gumbel score monotone in e/z
                if (rgt(e, z, m, s1e, s1z, s1i)) {
                    s2e = s1e; s2z = s1z; s2i = s1i;
                    s1e = e; s1z = z; s1i = m;
                } else if (rgt(e, z, m, s2e, s2z, s2i)) {
                    s2e = e; s2z = z; s2i = m;
                }
            }
        }
        #pragma unroll
        for (int o = 16; o > 0; o >>= 1) ssum += __shfl_xor_sync(0xffffffffu, ssum, o);
        // warp merge gumbel top2 (rational)
        #pragma unroll
        for (int o = 16; o > 0; o >>= 1) {
            float oe1 = __shfl_xor_sync(0xffffffffu, s1e, o);
            float oz1 = __shfl_xor_sync(0xffffffffu, s1z, o);
            int   oi1 = __shfl_xor_sync(0xffffffffu, s1i, o);
            float oe2 = __shfl_xor_sync(0xffffffffu, s2e, o);
            float oz2 = __shfl_xor_sync(0xffffffffu, s2z, o);
            int   oi2 = __shfl_xor_sync(0xffffffffu, s2i, o);
            if (rgt(oe1, oz1, oi1, s1e, s1z, s1i)) {
                if (rgt(s1e, s1z, s1i, oe2, oz2, oi2)) { s2e = s1e; s2z = s1z; s2i = s1i; }
                else { s2e = oe2; s2z = oz2; s2i = oi2; }
                s1e = oe1; s1z = oz1; s1i = oi1;
            } else {
                if (rgt(oe1, oz1, oi1, s2e, s2z, s2i)) { s2e = oe1; s2z = oz1; s2i = oi1; }
            }
        }

        // exact fp32 refinement of the 4 candidates
        int cands[4] = {h1i, h2i, s1i, s2i};
        float ex[4];
        const float* curp = g_cur + (size_t)n*DD + lane*8;
        #pragma unroll
        for (int t = 0; t < 4; t++) {
            const float* Ep = emb + (size_t)cands[t]*DD + lane*8;
            float s = 0.f;
            #pragma unroll
            for (int j = 0; j < 8; j++) s += curp[j]*Ep[j];
            #pragma unroll
            for (int o = 16; o > 0; o >>= 1) s += __shfl_xor_sync(0xffffffffu, s, o);
            ex[t] = 2.f*s - g_esq[cands[t]];
        }

        float inv = 1.f / ssum;
        #pragma unroll
        for (int ch = 0; ch < 8; ch++)
            #pragma unroll
            for (int j = 0; j < 4; j++) pAcc[ch][j] += dm[ch][j] * inv;

        if (lane == 0) {
            int kH = h1i; float vH = ex[0];
            if (ex[1] > vH || (ex[1] == vH && h2i < kH)) { kH = h2i; vH = ex[1]; }
            atomicAdd(&g_hist[kH], 1u);
            float sc0 = ex[2] + gumbel_of(Ur[s1i]);
            float sc1 = ex[3] + gumbel_of(Ur[s2i]);
            int kS = s1i;
            if (sc1 > sc0 || (sc1 == sc0 && s2i < s1i)) kS = s2i;
            g_idx[n] = kS;
            out[QSIZE + 2 + n] = (float)kS;
        }
    }
    #pragma unroll
    for (int ch = 0; ch < 8; ch++)
        #pragma unroll
        for (int j = 0; j < 4; j++) atomicAdd(&sAcc[ch*128 + lane*4 + j], pAcc[ch][j]);
    __syncthreads();
    for (int i = tid; i < MM; i += 256) atomicAdd(&g_avgp[i], sAcc[i]);
}

__global__ void k_finalize(float* __restrict__ out) {
    __shared__ float s1[MM];
    __shared__ float s2[MM];
    int m = threadIdx.x;
    float hp = (float)g_hist[m] * (1.f/(float)NN);
    float ap = g_avgp[m] * (1.f/(float)NN);
    s1[m] = -hp * log2f(hp + 1e-10f);
    s2[m] = -ap * log2f(ap + 1e-10f);
    __syncthreads();
    for (int s = 512; s > 0; s >>= 1) {
        if (m < s) { s1[m] += s1[m + s]; s2[m] += s2[m + s]; }
        __syncthreads();
    }
    if (m == 0) { out[QSIZE] = s1[0]; out[QSIZE + 1] = s2[0]; }
}

// ---------------- fuse2 (3xTF32, interleaved X, materialized W) --------------
#define F2_STG 3200
#define F2_SMEMB (64*130*4)

__global__ void __launch_bounds__(256) k_f2_tc(const float* __restrict__ a2p,
                                               float* __restrict__ out) {
    extern __shared__ float fs[];
    int tid = threadIdx.x, lane = tid & 31, warp = tid >> 5;
    int warpM = warp >> 2, warpN = warp & 3;
    int t0 = blockIdx.x*128, o0 = blockIdx.y*64, b = blockIdx.z;
    int ot0 = o0 >> 4;

    uint32_t sbase;
    asm("{ .reg .u64 t; cvta.to.shared.u64 t, %1; cvt.u32.u64 %0, t; }" : "=r"(sbase) : "l"(fs));

    auto issue = [&](int ic, int s) {
        uint32_t xd = sbase + (uint32_t)((s*F2_STG)*4);
        #pragma unroll
        for (int j = 0; j < 2; j++) {
            int idx = tid + j*256;
            int row = idx >> 6, q = idx & 63;
            const float2* sp = g_ctx2 + ((size_t)(b*DD + ic*8 + row))*TT + t0;
            asm volatile("cp.async.cg.shared.global [%0], [%1], 16;"
                :: "r"(xd + (uint32_t)((row*136 + q*2)*8)), "l"(sp + q*2));
        }
        if (tid < 128) {
            const float* wp = g_w2shh + ((size_t)ic*16 + ot0)*128;
            uint32_t wd = sbase + (uint32_t)((s*F2_STG + 2176)*4);
            asm volatile("cp.async.cg.shared.global [%0], [%1], 16;"
                :: "r"(wd + (uint32_t)(tid*16)), "l"(wp + tid*4));
        } else {
            int t2 = tid - 128;
            const float* wp = g_w2shl + ((size_t)ic*16 + ot0)*128;
            uint32_t wd = sbase + (uint32_t)((s*F2_STG + 2688)*4);
            asm volatile("cp.async.cg.shared.global [%0], [%1], 16;"
                :: "r"(wd + (uint32_t)(t2*16)), "l"(wp + t2*4));
        }
        asm volatile("cp.async.commit_group;");
    };

    float c[2][4][4] = {};
    issue(0, 0);
    issue(1, 1);

    for (int ic = 0; ic < 32; ic++) {
        int s = ic & 1;
        if (ic < 31) { asm volatile("cp.async.wait_group 1;"); }
        else         { asm volatile("cp.async.wait_group 0;"); }
        __syncthreads();
        const float2* X2 = (const float2*)(fs + s*F2_STG);
        const float* WH = fs + s*F2_STG + 2176;
        const float* WL = fs + s*F2_STG + 2688;
        int i0v = lane & 3, trow = lane >> 2;

        uint32_t ah[2][4], al[2][4];
        #pragma unroll
        for (int mf = 0; mf < 2; mf++) {
            float4 vh = *(const float4*)&WH[(warpM*2 + mf)*128 + lane*4];
            float4 vl = *(const float4*)&WL[(warpM*2 + mf)*128 + lane*4];
            ah[mf][0] = __float_as_uint(vh.x); ah[mf][1] = __float_as_uint(vh.y);
            ah[mf][2] = __float_as_uint(vh.z); ah[mf][3] = __float_as_uint(vh.w);
            al[mf][0] = __float_as_uint(vl.x); al[mf][1] = __float_as_uint(vl.y);
            al[mf][2] = __float_as_uint(vl.z); al[mf][3] = __float_as_uint(vl.w);
        }
        uint32_t bh[4][2], bl[4][2];
        #pragma unroll
        for (int nf = 0; nf < 4; nf++) {
            int toff = warpN*32 + nf*8 + trow;
            float2 v0 = X2[i0v*136 + toff];
            float2 v1 = X2[(i0v + 4)*136 + toff];
            bh[nf][0] = __float_as_uint(v0.x); bl[nf][0] = __float_as_uint(v0.y);
            bh[nf][1] = __float_as_uint(v1.x); bl[nf][1] = __float_as_uint(v1.y);
        }
        #pragma unroll
        for (int mf = 0; mf < 2; mf++) {
            #pragma unroll
            for (int nf = 0; nf < 4; nf++) {
                MMA8(c[mf][nf], ah[mf][0], ah[mf][1], ah[mf][2], ah[mf][3], bh[nf][0], bh[nf][1]);
                MMA8(c[mf][nf], ah[mf][0], ah[mf][1], ah[mf][2], ah[mf][3], bl[nf][0], bl[nf][1]);
                MMA8(c[mf][nf], al[mf][0], al[mf][1], al[mf][2], al[mf][3], bh[nf][0], bh[nf][1]);
            }
        }
        __syncthreads();
        if (ic + 2 < 32) issue(ic + 2, s);
    }

    #pragma unroll
    for (int mf = 0; mf < 2; mf++) {
        int r = warpM*32 + mf*16 + (lane >> 2);
        #pragma unroll
        for (int nf = 0; nf < 4; nf++) {
            int tg = warpN*32 + nf*8 + (lane & 3)*2;
            *(float2*)&fs[r*130 + tg]       = make_float2(c[mf][nf][0], c[mf][nf][1]);
            *(float2*)&fs[(r + 8)*130 + tg] = make_float2(c[mf][nf][2], c[mf][nf][3]);
        }
    }
    __syncthreads();
    float a2v = *a2p;
    int nl = tid >> 1, half = tid & 1;
    size_t n = (size_t)b*TT + t0 + nl;
    int mi = g_idx[n];
    const float* w2e = g_W2E + (size_t)mi*DD + o0 + half*32;
    float* op = out + n*DD + o0 + half*32;
    #pragma unroll
    for (int j = 0; j < 8; j++) {
        float4 w4 = *(const float4*)&w2e[j*4];
        float4 v;
        float u;
        u = fs[(half*32 + j*4 + 0)*130 + nl] + w4.x; v.x = (u >= 0.f) ? u : a2v*u;
        u = fs[(half*32 + j*4 + 1)*130 + nl] + w4.y; v.y = (u >= 0.f) ? u : a2v*u;
        u = fs[(half*32 + j*4 + 2)*130 + nl] + w4.z; v.z = (u >= 0.f) ? u : a2v*u;
        u = fs[(half*32 + j*4 + 3)*130 + nl] + w4.w; v.w = (u >= 0.f) ? u : a2v*u;
        *(float4*)&op[j*4] = v;
    }
}

// ---------------- launch -----------------------------------------------------
extern "C" void kernel_launch(void* const* d_in, const int* in_sizes, int n_in,
                              void* d_out, int out_size) {
    const float* x     = (const float*)d_in[0];
    const float* noise = (const float*)d_in[1];
    const float* gum   = (const float*)d_in[2];
    const int*   epo   = (const int*)  d_in[3];
    const float* emb   = (const float*)d_in[4];
    const float* wctx  = (const float*)d_in[5];
    const float* wf1   = (const float*)d_in[6];
    const float* a1    = (const float*)d_in[7];
    const float* wf2   = (const float*)d_in[8];
    const float* a2    = (const float*)d_in[9];
    float* out = (float*)d_out;

    cudaFuncSetAttribute(k_conv_tc, cudaFuncAttributeMaxDynamicSharedMemorySize, CV_SMEMB);
    cudaFuncSetAttribute(k_f1_tc, cudaFuncAttributeMaxDynamicSharedMemorySize, F1_SMEMB);
    cudaFuncSetAttribute(k_dist_b, cudaFuncAttributeMaxDynamicSharedMemorySize, DB_SMEMB);
    cudaFuncSetAttribute(k_f2_tc, cudaFuncAttributeMaxDynamicSharedMemorySize, F2_SMEMB);

    dim3 tb32(32, 8);

    k_scale<<<BB, 256>>>(x, epo);                                   // 0
    k_noisy<<<dim3((LL + 31)/32, DD/32, BB), tb32>>>(x, noise);     // 1
    k_prep_w<<<2560, 256>>>(wctx, wf1, wf2);                        // 2
    k_conv_tc<<<dim3(TT/128, 4, BB), 256, CV_SMEMB>>>();            // 3 <- capture
    k_xt<<<dim3(TT/32, DD/32, BB), tb32>>>(x);
    k_f1_tc<<<dim3(TT/128, DD/64, BB), 256, F1_SMEMB>>>(a1);
    k_transp<<<dim3(DD/32, MM/32), tb32>>>(emb, MM, DD, 0);         // ET
    k_transp<<<dim3(2*DD/32, DD/32), tb32>>>(wf2, DD, 2*DD, 1);     // w2T
    k_prep_e<<<MM, 256>>>(emb);
    k_gemm_w2e<<<dim3(MM/64, DD/64), 256>>>();
    k_dist_b<<<dim3(NN/128, MM/128), 256, DB_SMEMB>>>();
    k_rowstats<<<NN/16, 256>>>(gum, emb, out);
    k_finalize<<<1, MM>>>(out);
    k_f2_tc<<<dim3(TT/128, DD/64, BB), 256, F2_SMEMB>>>(a2, out);
}

// round 16
// speedup vs baseline: 1.0206x; 1.0011x over previous
#include <cuda_runtime.h>
#include <cuda_bf16.h>
#include <math.h>
#include <stdint.h>

#define BB 8
#define TT 4096
#define DD 256
#define MM 1024
#define CTX 7
#define LL (TT - 1 + CTX)      /* 4102 */
#define LLP 4104               /* padded stride */
#define NN (BB*TT)             /* 32768 */
#define QSIZE (NN*DD)          /* 8388608 */

// ---------------- scratch ----------------------------------------------------
__device__ __align__(16) float2 g_xt2[BB*DD*TT];        // x^T as (tf32hi, lo)
__device__ __align__(16) float2 g_noisy2[BB*DD*LLP];    // noisy ctx-in (hi, lo)
__device__ __align__(16) float2 g_ctx2[BB*DD*TT];       // conv out (hi, lo)
__device__ __align__(16) float g_wch[DD*DD*CTX];        // w_ctx hi, A-frag shuffled
__device__ __align__(16) float g_wcl[DD*DD*CTX];
__device__ __align__(16) float g_w1shh[2*DD*DD];
__device__ __align__(16) float g_w1shl[2*DD*DD];
__device__ __align__(16) float g_w2shh[DD*DD];
__device__ __align__(16) float g_w2shl[DD*DD];
__device__ __align__(16) float g_cur[(size_t)NN*DD];    // fuse1 out, exact fp32
__device__ __align__(16) __nv_bfloat16 g_cur_bh[(size_t)NN*DD];
__device__ __align__(16) __nv_bfloat16 g_cur_bl[(size_t)NN*DD];
__device__ __align__(16) __nv_bfloat16 g_E_bh[MM*DD];
__device__ __align__(16) __nv_bfloat16 g_E_bl[MM*DD];
__device__ __align__(16) float g_G[(size_t)NN*MM];
__device__ __align__(16) float g_ET[DD*MM];
__device__ __align__(16) float g_w2T[2*DD*DD];
__device__ __align__(16) float g_W2E[MM*DD];
__device__ __align__(16) float g_esq[MM];
__device__ float g_scale[BB];
__device__ int   g_idx[NN];
__device__ unsigned int g_hist[MM];
__device__ float g_avgp[MM];

__device__ __forceinline__ float tf32_hi(float v) {
    uint32_t b;
    asm("cvt.rna.tf32.f32 %0, %1;" : "=r"(b) : "f"(v));
    return __uint_as_float(b);
}

#define MMA8(d, a0,a1,a2,a3, b0,b1) \
    asm volatile("mma.sync.aligned.m16n8k8.row.col.f32.tf32.tf32.f32 " \
        "{%0,%1,%2,%3}, {%4,%5,%6,%7}, {%8,%9}, {%0,%1,%2,%3};" \
        : "+f"((d)[0]), "+f"((d)[1]), "+f"((d)[2]), "+f"((d)[3]) \
        : "r"(a0), "r"(a1), "r"(a2), "r"(a3), "r"(b0), "r"(b1))

#define MMA16B(d, a, b) \
    asm volatile("mma.sync.aligned.m16n8k16.row.col.f32.bf16.bf16.f32 " \
        "{%0,%1,%2,%3}, {%4,%5,%6,%7}, {%8,%9}, {%0,%1,%2,%3};" \
        : "+f"((d)[0]), "+f"((d)[1]), "+f"((d)[2]), "+f"((d)[3]) \
        : "r"((a)[0]), "r"((a)[1]), "r"((a)[2]), "r"((a)[3]), "r"((b)[0]), "r"((b)[1]))

// ---------------- fused prep kernels -----------------------------------------
__global__ void k_prep_e(const float* __restrict__ E) {
    __shared__ float sm[8];
    int m = blockIdx.x, tid = threadIdx.x;
    float v = E[(size_t)m*DD + tid];
    __nv_bfloat16 h = __float2bfloat16(v);
    g_E_bh[(size_t)m*DD + tid] = h;
    g_E_bl[(size_t)m*DD + tid] = __float2bfloat16(v - __bfloat162float(h));
    float s = v*v;
    #pragma unroll
    for (int o = 16; o > 0; o >>= 1) s += __shfl_down_sync(0xffffffffu, s, o);
    if ((tid & 31) == 0) sm[tid >> 5] = s;
    __syncthreads();
    if (tid == 0) {
        float t = 0.f;
        #pragma unroll
        for (int w = 0; w < 8; w++) t += sm[w];
        g_esq[m] = t;
    }
    if (m < 4) { g_hist[m*256 + tid] = 0u; g_avgp[m*256 + tid] = 0.f; }
}

__global__ void k_prep_w(const float* __restrict__ wctx,
                         const float* __restrict__ wf1,
                         const float* __restrict__ wf2) {
    int b = blockIdx.x, tid = threadIdx.x;
    if (b < 1792) {
        int idx = b*256 + tid;
        int o = idx / (DD*CTX);
        int rem = idx - o*(DD*CTX);
        int i = rem / CTX, kk = rem - i*CTX;
        float v = wctx[idx];
        float h = tf32_hi(v);
        int ic = i >> 3, il = i & 7;
        int otile = o >> 4, oloc = o & 15;
        int lane = (oloc & 7)*4 + (il & 3);
        int reg = (oloc >> 3) + 2*(il >> 2);
        int d = ((ic*7 + kk)*16 + otile)*128 + lane*4 + reg;
        g_wch[d] = h;
        g_wcl[d] = tf32_hi(v - h);
    } else if (b < 2304) {
        int idx = (b - 1792)*256 + tid;
        int o = idx >> 9, k = idx & 511;
        float v = wf1[idx];
        float h = tf32_hi(v);
        int ks = k >> 3, il = k & 7;
        int otile = o >> 4, oloc = o & 15;
        int lane = (oloc & 7)*4 + (il & 3);
        int reg = (oloc >> 3) + 2*(il >> 2);
        int d = (ks*16 + otile)*128 + lane*4 + reg;
        g_w1shh[d] = h;
        g_w1shl[d] = tf32_hi(v - h);
    } else {
        int idx = (b - 2304)*256 + tid;
        int o = idx >> 8, k = idx & 255;
        int ic = k >> 3, il = k & 7;
        int otile = o >> 4, oloc = o & 15;
        int lane = (oloc & 7)*4 + (il & 3);
        int reg = (oloc >> 3) + 2*(il >> 2);
        float v = wf2[o*2*DD + DD + k];
        float h = tf32_hi(v);
        int d = (ic*16 + otile)*128 + lane*4 + reg;
        g_w2shh[d] = h;
        g_w2shl[d] = tf32_hi(v - h);
    }
}

__global__ void k_transp(const float* __restrict__ src, int rows, int cols, int which) {
    __shared__ float s[32][33];
    float* dst = (which == 0) ? g_ET : g_w2T;
    int c0 = blockIdx.x*32, r0 = blockIdx.y*32;
    int tx = threadIdx.x, ty = threadIdx.y;
    #pragma unroll
    for (int j = 0; j < 4; j++) {
        int r = r0 + ty + j*8, c = c0 + tx;
        s[ty + j*8][tx] = (r < rows && c < cols) ? src[(size_t)r*cols + c] : 0.f;
    }
    __syncthreads();
    #pragma unroll
    for (int j = 0; j < 4; j++) {
        int c = c0 + ty + j*8, r = r0 + tx;
        if (c < cols && r < rows) dst[(size_t)c*rows + r] = s[tx][ty + j*8];
    }
}

__global__ void k_scale(const float* __restrict__ x, const int* __restrict__ epo_p) {
    int b = blockIdx.x;
    const float* xb = x + (size_t)b*TT*DD;
    float s = 0.f;
    int tot = (TT-1)*DD;
    for (int i = threadIdx.x; i < tot; i += blockDim.x) { float v = xb[i]; s += v*v; }
    __shared__ float sm[8];
    #pragma unroll
    for (int o = 16; o > 0; o >>= 1) s += __shfl_down_sync(0xffffffffu, s, o);
    if ((threadIdx.x & 31) == 0) sm[threadIdx.x >> 5] = s;
    __syncthreads();
    if (threadIdx.x == 0) {
        float t = 0.f;
        for (int w = 0; w < 8; w++) t += sm[w];
        int iv = epo_p[0];
        float ef = (iv >= 0 && iv < 100000) ? (float)iv : __int_as_float(iv);
        float sc = sqrtf(t / (float)(DD*LL));
        g_scale[b] = 0.5f * sc * exp2f(-ef * 0.1f);
    }
}

// x -> xt2 (hi,lo) [b][d][t]
__global__ void k_xt(const float* __restrict__ x) {
    __shared__ float s[32][33];
    int b = blockIdx.z, t0 = blockIdx.x*32, d0 = blockIdx.y*32;
    int tx = threadIdx.x, ty = threadIdx.y;
    #pragma unroll
    for (int j = 0; j < 4; j++) {
        int t = t0 + ty + j*8;
        s[ty + j*8][tx] = x[((size_t)b*TT + t)*DD + d0 + tx];
    }
    __syncthreads();
    #pragma unroll
    for (int j = 0; j < 4; j++) {
        int d = d0 + ty + j*8;
        float v = s[tx][ty + j*8];
        float h = tf32_hi(v);
        g_xt2[((size_t)b*DD + d)*TT + t0 + tx] = make_float2(h, tf32_hi(v - h));
    }
}

__global__ void k_noisy(const float* __restrict__ x, const float* __restrict__ noise) {
    __shared__ float s[32][33];
    int b = blockIdx.z, l0 = blockIdx.x*32, i0 = blockIdx.y*32;
    int tx = threadIdx.x, ty = threadIdx.y;
    float coef = g_scale[b];
    #pragma unroll
    for (int j = 0; j < 4; j++) {
        int row = ty + j*8;
        int t = l0 + row - CTX;
        float v = (t >= 0 && t < TT-1) ? x[((size_t)b*TT + t)*DD + i0 + tx] : 0.f;
        s[row][tx] = v;
    }
    __syncthreads();
    #pragma unroll
    for (int j = 0; j < 4; j++) {
        int i = i0 + ty + j*8, l = l0 + tx;
        if (l < LL) {
            float v = s[tx][ty + j*8] + coef * noise[((size_t)b*DD + i)*LL + l];
            float h = tf32_hi(v);
            g_noisy2[((size_t)b*DD + i)*LLP + l] = make_float2(h, tf32_hi(v - h));
        }
    }
}

// ---------------- conv (3xTF32, o64 x t256 block, warp tile o32 x t64) -------
// stage floats: X2 8 x 264 f2 = 4224 + WH 3584 + WL 3584 = 11392
#define CV_STG 11392
#define CV_SMEMB (2*CV_STG*4)   /* 91136 */

__global__ void __launch_bounds__(256, 2) k_conv_tc() {
    extern __shared__ float cs[];
    int tid = threadIdx.x, lane = tid & 31, warp = tid >> 5;
    int warpM = warp >> 2, warpN = warp & 3;
    int t0 = blockIdx.x*256, o0 = blockIdx.y*64, b = blockIdx.z;
    int ot0 = o0 >> 4;

    uint32_t sbase;
    asm("{ .reg .u64 t; cvta.to.shared.u64 t, %1; cvt.u32.u64 %0, t; }" : "=r"(sbase) : "l"(cs));

    auto issue = [&](int ic, int s) {
        const float2* xp = g_noisy2 + ((size_t)(b*DD + ic*8))*LLP + t0;
        uint32_t xd = sbase + (uint32_t)((s*CV_STG)*4);
        for (int idx = tid; idx < 1056; idx += 256) {
            int row = idx / 132, q = idx - row*132;
            asm volatile("cp.async.cg.shared.global [%0], [%1], 16;"
                :: "r"(xd + (uint32_t)((row*264 + q*2)*8)), "l"(xp + (size_t)row*LLP + q*2));
        }
        const float* wh = g_wch + ((size_t)(ic*7)*16 + ot0)*128;
        const float* wl = g_wcl + ((size_t)(ic*7)*16 + ot0)*128;
        uint32_t wdh = sbase + (uint32_t)((s*CV_STG + 4224)*4);
        uint32_t wdl = wdh + 3584*4;
        for (int idx = tid; idx < 896; idx += 256) {
            int kk = idx >> 7, q = idx & 127;
            asm volatile("cp.async.cg.shared.global [%0], [%1], 16;"
                :: "r"(wdh + (uint32_t)((kk*512 + q*4)*4)), "l"(wh + kk*2048 + q*4));
            asm volatile("cp.async.cg.shared.global [%0], [%1], 16;"
                :: "r"(wdl + (uint32_t)((kk*512 + q*4)*4)), "l"(wl + kk*2048 + q*4));
        }
        asm volatile("cp.async.commit_group;");
    };

    float c[2][8][4] = {};
    issue(0, 0);
    issue(1, 1);

    for (int ic = 0; ic < 32; ic++) {
        int s = ic & 1;
        if (ic < 31) { asm volatile("cp.async.wait_group 1;"); }
        else         { asm volatile("cp.async.wait_group 0;"); }
        __syncthreads();
        const float2* X2 = (const float2*)(cs + s*CV_STG);
        const float* WH = cs + s*CV_STG + 4224;
        const float* WL = cs + s*CV_STG + 7808;
        int i0v = lane & 3, trow = lane >> 2;

        #pragma unroll
        for (int kk = 0; kk < 7; kk++) {
            uint32_t ah[2][4], al[2][4];
            #pragma unroll
            for (int mf = 0; mf < 2; mf++) {
                float4 vh = *(const float4*)&WH[kk*512 + (warpM*2 + mf)*128 + lane*4];
                float4 vl = *(const float4*)&WL[kk*512 + (warpM*2 + mf)*128 + lane*4];
                ah[mf][0] = __float_as_uint(vh.x); ah[mf][1] = __float_as_uint(vh.y);
                ah[mf][2] = __float_as_uint(vh.z); ah[mf][3] = __float_as_uint(vh.w);
                al[mf][0] = __float_as_uint(vl.x); al[mf][1] = __float_as_uint(vl.y);
                al[mf][2] = __float_as_uint(vl.z); al[mf][3] = __float_as_uint(vl.w);
            }
            #pragma unroll
            for (int nf = 0; nf < 8; nf++) {
                int toff = warpN*64 + nf*8 + trow + kk;
                float2 v0 = X2[i0v*264 + toff];
                float2 v1 = X2[(i0v + 4)*264 + toff];
                uint32_t bh0 = __float_as_uint(v0.x), bl0 = __float_as_uint(v0.y);
                uint32_t bh1 = __float_as_uint(v1.x), bl1 = __float_as_uint(v1.y);
                #pragma unroll
                for (int mf = 0; mf < 2; mf++) {
                    MMA8(c[mf][nf], ah[mf][0], ah[mf][1], ah[mf][2], ah[mf][3], bh0, bh1);
                    MMA8(c[mf][nf], ah[mf][0], ah[mf][1], ah[mf][2], ah[mf][3], bl0, bl1);
                    MMA8(c[mf][nf], al[mf][0], al[mf][1], al[mf][2], al[mf][3], bh0, bh1);
                }
            }
        }
        __syncthreads();
        if (ic + 2 < 32) issue(ic + 2, s);
    }

    // epilogue: write ctx as interleaved (hi,lo)
    #pragma unroll
    for (int mf = 0; mf < 2; mf++) {
        int r = o0 + warpM*32 + mf*16 + (lane >> 2);
        #pragma unroll
        for (int nf = 0; nf < 8; nf++) {
            int tg = t0 + warpN*64 + nf*8 + (lane & 3)*2;
            float v0 = c[mf][nf][0], v1 = c[mf][nf][1];
            float v2 = c[mf][nf][2], v3 = c[mf][nf][3];
            float h0 = tf32_hi(v0), h1 = tf32_hi(v1), h2 = tf32_hi(v2), h3 = tf32_hi(v3);
            size_t o1 = ((size_t)b*DD + r)*TT + tg;
            size_t o2 = ((size_t)b*DD + r + 8)*TT + tg;
            *(float4*)&g_ctx2[o1] = make_float4(h0, tf32_hi(v0 - h0), h1, tf32_hi(v1 - h1));
            *(float4*)&g_ctx2[o2] = make_float4(h2, tf32_hi(v2 - h2), h3, tf32_hi(v3 - h3));
        }
    }
}

// ---------------- fuse1 on tensor cores (3xTF32, interleaved X) --------------
#define F1_STG 6400
#define F1_SMEMB (2*F1_STG*4)

__global__ void __launch_bounds__(256, 2) k_f1_tc(const float* __restrict__ a1p) {
    extern __shared__ float fs[];
    int tid = threadIdx.x, lane = tid & 31, warp = tid >> 5;
    int warpM = warp >> 2, warpN = warp & 3;
    int t0 = blockIdx.x*128, o0 = blockIdx.y*64, b = blockIdx.z;
    int ot0 = o0 >> 4;

    uint32_t sbase;
    asm("{ .reg .u64 t; cvta.to.shared.u64 t, %1; cvt.u32.u64 %0, t; }" : "=r"(sbase) : "l"(fs));

    auto issue = [&](int cchunk, int s) {
        uint32_t xd = sbase + (uint32_t)((s*F1_STG)*4);
        #pragma unroll
        for (int j = 0; j < 4; j++) {
            int idx = tid + j*256;
            int row = idx >> 6, q = idx & 63;
            int d = cchunk*16 + row;
            const float2* sp = (d < DD) ? (g_xt2 + ((size_t)b*DD + d)*TT + t0)
                                        : (g_ctx2 + ((size_t)b*DD + d - DD)*TT + t0);
            asm volatile("cp.async.cg.shared.global [%0], [%1], 16;"
                :: "r"(xd + (uint32_t)((row*136 + q*2)*8)), "l"(sp + q*2));
        }
        const float* wh = g_w1shh + ((size_t)(cchunk*2)*16 + ot0)*128;
        const float* wl = g_w1shl + ((size_t)(cchunk*2)*16 + ot0)*128;
        uint32_t wdh = sbase + (uint32_t)((s*F1_STG + 4352)*4);
        uint32_t wdl = wdh + 1024*4;
        {
            int sl8 = tid >> 7, q = tid & 127;
            asm volatile("cp.async.cg.shared.global [%0], [%1], 16;"
                :: "r"(wdh + (uint32_t)(tid*16)), "l"(wh + sl8*2048 + q*4));
            asm volatile("cp.async.cg.shared.global [%0], [%1], 16;"
                :: "r"(wdl + (uint32_t)(tid*16)), "l"(wl + sl8*2048 + q*4));
        }
        asm volatile("cp.async.commit_group;");
    };

    float c[2][4][4] = {};
    issue(0, 0);
    issue(1, 1);

    for (int cc = 0; cc < 32; cc++) {
        int s = cc & 1;
        if (cc < 31) { asm volatile("cp.async.wait_group 1;"); }
        else         { asm volatile("cp.async.wait_group 0;"); }
        __syncthreads();
        const float2* X2 = (const float2*)(fs + s*F1_STG);
        const float* WH = fs + s*F1_STG + 4352;
        const float* WL = fs + s*F1_STG + 5376;
        int i0v = lane & 3, trow = lane >> 2;

        #pragma unroll
        for (int sl8 = 0; sl8 < 2; sl8++) {
            uint32_t ah[2][4], al[2][4];
            #pragma unroll
            for (int mf = 0; mf < 2; mf++) {
                float4 vh = *(const float4*)&WH[sl8*512 + (warpM*2 + mf)*128 + lane*4];
                float4 vl = *(const float4*)&WL[sl8*512 + (warpM*2 + mf)*128 + lane*4];
                ah[mf][0] = __float_as_uint(vh.x); ah[mf][1] = __float_as_uint(vh.y);
                ah[mf][2] = __float_as_uint(vh.z); ah[mf][3] = __float_as_uint(vh.w);
                al[mf][0] = __float_as_uint(vl.x); al[mf][1] = __float_as_uint(vl.y);
                al[mf][2] = __float_as_uint(vl.z); al[mf][3] = __float_as_uint(vl.w);
            }
            uint32_t bh[4][2], bl[4][2];
            #pragma unroll
            for (int nf = 0; nf < 4; nf++) {
                int toff = warpN*32 + nf*8 + trow;
                int rbase = sl8*8 + i0v;
                float2 v0 = X2[rbase*136 + toff];
                float2 v1 = X2[(rbase + 4)*136 + toff];
                bh[nf][0] = __float_as_uint(v0.x); bl[nf][0] = __float_as_uint(v0.y);
                bh[nf][1] = __float_as_uint(v1.x); bl[nf][1] = __float_as_uint(v1.y);
            }
            #pragma unroll
            for (int mf = 0; mf < 2; mf++) {
                #pragma unroll
                for (int nf = 0; nf < 4; nf++) {
                    MMA8(c[mf][nf], ah[mf][0], ah[mf][1], ah[mf][2], ah[mf][3], bh[nf][0], bh[nf][1]);
                    MMA8(c[mf][nf], ah[mf][0], ah[mf][1], ah[mf][2], ah[mf][3], bl[nf][0], bl[nf][1]);
                    MMA8(c[mf][nf], al[mf][0], al[mf][1], al[mf][2], al[mf][3], bh[nf][0], bh[nf][1]);
                }
            }
        }
        __syncthreads();
        if (cc + 2 < 32) issue(cc + 2, s);
    }

    float a1 = *a1p;
    #pragma unroll
    for (int mf = 0; mf < 2; mf++) {
        int r = warpM*32 + mf*16 + (lane >> 2);
        #pragma unroll
        for (int nf = 0; nf < 4; nf++) {
            int tg = warpN*32 + nf*8 + (lane & 3)*2;
            float v0 = c[mf][nf][0]; v0 = (v0 >= 0.f) ? v0 : a1*v0;
            float v1 = c[mf][nf][1]; v1 = (v1 >= 0.f) ? v1 : a1*v1;
            float v2 = c[mf][nf][2]; v2 = (v2 >= 0.f) ? v2 : a1*v2;
            float v3 = c[mf][nf][3]; v3 = (v3 >= 0.f) ? v3 : a1*v3;
            *(float2*)&fs[r*130 + tg]       = make_float2(v0, v1);
            *(float2*)&fs[(r + 8)*130 + tg] = make_float2(v2, v3);
        }
    }
    __syncthreads();
    int nl = tid >> 1, half = tid & 1;
    size_t n = (size_t)b*TT + t0 + nl;
    float* cp = g_cur + n*DD + o0 + half*32;
    __nv_bfloat16* bhp = g_cur_bh + n*DD + o0 + half*32;
    __nv_bfloat16* blp = g_cur_bl + n*DD + o0 + half*32;
    #pragma unroll
    for (int j = 0; j < 8; j++) {
        float4 v;
        v.x = fs[(half*32 + j*4 + 0)*130 + nl];
        v.y = fs[(half*32 + j*4 + 1)*130 + nl];
        v.z = fs[(half*32 + j*4 + 2)*130 + nl];
        v.w = fs[(half*32 + j*4 + 3)*130 + nl];
        *(float4*)&cp[j*4] = v;
        float vv[4] = {v.x, v.y, v.z, v.w};
        __nv_bfloat16 bh4[4], bl4[4];
        #pragma unroll
        for (int q = 0; q < 4; q++) {
            bh4[q] = __float2bfloat16(vv[q]);
            bl4[q] = __float2bfloat16(vv[q] - __bfloat162float(bh4[q]));
        }
        *(uint2*)&bhp[j*4] = *(uint2*)bh4;
        *(uint2*)&blp[j*4] = *(uint2*)bl4;
    }
}

// ---------------- W2E GEMM (small) -------------------------------------------
__global__ void __launch_bounds__(256) k_gemm_w2e() {
    __shared__ float sA[16][68];
    __shared__ float sB[16][68];
    int i0 = blockIdx.x*64, j0 = blockIdx.y*64;
    int tid = threadIdx.x;
    int tx = tid & 15, ty = tid >> 4;
    int kl = tid >> 4, nl4 = (tid & 15)*4;
    float acc[4][4] = {};
    for (int kc = 0; kc < DD; kc += 16) {
        *(float4*)&sA[kl][nl4] = *(const float4*)(g_ET  + (size_t)(kc + kl)*MM + i0 + nl4);
        *(float4*)&sB[kl][nl4] = *(const float4*)(g_w2T + (size_t)(kc + kl)*DD + j0 + nl4);
        __syncthreads();
        #pragma unroll
        for (int k = 0; k < 16; k++) {
            float4 av = *(const float4*)&sA[k][4*tx];
            float4 bv = *(const float4*)&sB[k][4*ty];
            float ar[4] = {av.x, av.y, av.z, av.w};
            float br[4] = {bv.x, bv.y, bv.z, bv.w};
            #pragma unroll
            for (int a = 0; a < 4; a++)
                #pragma unroll
                for (int cc = 0; cc < 4; cc++)
                    acc[a][cc] += br[a] * ar[cc];
        }
        __syncthreads();
    }
    #pragma unroll
    for (int cc = 0; cc < 4; cc++) {
        int i = i0 + 4*tx + cc;
        float4 v = make_float4(acc[0][cc], acc[1][cc], acc[2][cc], acc[3][cc]);
        *(float4*)&g_W2E[(size_t)i*DD + j0 + 4*ty] = v;
    }
}

// ---------------- dist GEMM via mma.sync bf16 (3xBF16, k16) ------------------
#define DB_ROWW 20
#define DB_ARRW (128*DB_ROWW)
#define DB_STGW (4*DB_ARRW)
#define DB_SMEMB (2*DB_STGW*4)

__global__ void __launch_bounds__(256, 2) k_dist_b() {
    extern __shared__ uint32_t dsm[];
    int tid = threadIdx.x, lane = tid & 31, warp = tid >> 5;
    int warpM = warp >> 2, warpN = warp & 3;
    int n0 = blockIdx.x*128, m0 = blockIdx.y*128;

    uint32_t sbase;
    asm("{ .reg .u64 t; cvta.to.shared.u64 t, %1; cvt.u32.u64 %0, t; }" : "=r"(sbase) : "l"(dsm));

    const __nv_bfloat16* srcs[4] = {
        g_cur_bh + (size_t)n0*DD, g_cur_bl + (size_t)n0*DD,
        g_E_bh   + (size_t)m0*DD, g_E_bl   + (size_t)m0*DD };

    auto issue = [&](int kc, int s) {
        #pragma unroll
        for (int a = 0; a < 4; a++) {
            uint32_t dstb = sbase + (uint32_t)((s*DB_STGW + a*DB_ARRW)*4);
            #pragma unroll
            for (int j = 0; j < 2; j++) {
                int cid = tid + j*256;
                int row = cid >> 2, q = cid & 3;
                uint32_t dst = dstb + (uint32_t)(row*80 + q*16);
                const __nv_bfloat16* src = srcs[a] + (size_t)row*DD + kc + q*8;
                asm volatile("cp.async.cg.shared.global [%0], [%1], 16;"
                             :: "r"(dst), "l"(src));
            }
        }
        asm volatile("cp.async.commit_group;");
    };

    float c[4][4][4] = {};
    issue(0, 0);

    int gr = lane >> 2, lc = lane & 3;
    for (int it = 0; it < 8; it++) {
        int s = it & 1;
        if (it + 1 < 8) issue((it + 1)*32, s ^ 1);
        if (it + 1 < 8) { asm volatile("cp.async.wait_group 1;"); }
        else            { asm volatile("cp.async.wait_group 0;"); }
        __syncthreads();

        const uint32_t* sAh = dsm + s*DB_STGW;
        const uint32_t* sAl = sAh + DB_ARRW;
        const uint32_t* sBh = sAh + 2*DB_ARRW;
        const uint32_t* sBl = sAh + 3*DB_ARRW;

        #pragma unroll
        for (int ks = 0; ks < 2; ks++) {
            int wb = ks*8 + lc;
            uint32_t ah[4][4], al[4][4], bh[4][2], bl[4][2];
            #pragma unroll
            for (int mf = 0; mf < 4; mf++) {
                int r1 = (warpM*64 + mf*16 + gr)*DB_ROWW, r2 = r1 + 8*DB_ROWW;
                ah[mf][0] = sAh[r1 + wb];     ah[mf][1] = sAh[r2 + wb];
                ah[mf][2] = sAh[r1 + wb + 4]; ah[mf][3] = sAh[r2 + wb + 4];
                al[mf][0] = sAl[r1 + wb];     al[mf][1] = sAl[r2 + wb];
                al[mf][2] = sAl[r1 + wb + 4]; al[mf][3] = sAl[r2 + wb + 4];
            }
            #pragma unroll
            for (int nf = 0; nf < 4; nf++) {
                int rn = (warpN*32 + nf*8 + gr)*DB_ROWW;
                bh[nf][0] = sBh[rn + wb]; bh[nf][1] = sBh[rn + wb + 4];
                bl[nf][0] = sBl[rn + wb]; bl[nf][1] = sBl[rn + wb + 4];
            }
            #pragma unroll
            for (int mf = 0; mf < 4; mf++) {
                #pragma unroll
                for (int nf = 0; nf < 4; nf++) {
                    MMA16B(c[mf][nf], ah[mf], bh[nf]);
                    MMA16B(c[mf][nf], ah[mf], bl[nf]);
                    MMA16B(c[mf][nf], al[mf], bh[nf]);
                }
            }
        }
        __syncthreads();
    }

    #pragma unroll
    for (int mf = 0; mf < 4; mf++) {
        int r1 = n0 + warpM*64 + mf*16 + gr;
        #pragma unroll
        for (int nf = 0; nf < 4; nf++) {
            int gc = m0 + warpN*32 + nf*8 + lc*2;
            *(float2*)&g_G[(size_t)r1*MM + gc]       = make_float2(c[mf][nf][0], c[mf][nf][1]);
            *(float2*)&g_G[(size_t)(r1 + 8)*MM + gc] = make_float2(c[mf][nf][2], c[mf][nf][3]);
        }
    }
}

// ---------------- per-row stats (R10 exact form) ------------------------------
__device__ __forceinline__ float gumbel_of(float u) {
    u = fminf(fmaxf(u, 1e-10f), 1.f - 1e-7f);
    return -__logf(-__logf(u));
}

__global__ void __launch_bounds__(256) k_rowstats(const float* __restrict__ gum,
                                                  const float* __restrict__ emb,
                                                  float* __restrict__ out) {
    __shared__ float sAcc[MM];
    int tid = threadIdx.x, wid = tid >> 5, lane = tid & 31;
    for (int i = tid; i < MM; i += 256) sAcc[i] = 0.f;
    __syncthreads();

    float esq_r[8][4];
    #pragma unroll
    for (int ch = 0; ch < 8; ch++) {
        float4 v = *(const float4*)&g_esq[ch*128 + lane*4];
        esq_r[ch][0] = v.x; esq_r[ch][1] = v.y; esq_r[ch][2] = v.z; esq_r[ch][3] = v.w;
    }
    float pAcc[8][4] = {};
    int nbase = blockIdx.x*16 + wid*2;

    #pragma unroll
    for (int r = 0; r < 2; r++) {
        int n = nbase + r;
        const float* Gr = g_G + (size_t)n*MM;
        const float* Ur = gum + (size_t)n*MM;
        float dm[8][4];
        float h1v = -3.4e38f, h2v = -3.4e38f; int h1i = 0x7fffffff, h2i = 0x7fffffff;
        float s1v = -3.4e38f, s2v = -3.4e38f; int s1i = 0x7fffffff, s2i = 0x7fffffff;
        #pragma unroll
        for (int ch = 0; ch < 8; ch++) {
            float4 g4 = *(const float4*)&Gr[ch*128 + lane*4];
            float4 u4 = *(const float4*)&Ur[ch*128 + lane*4];
            float gg[4] = {g4.x, g4.y, g4.z, g4.w};
            float uu[4] = {u4.x, u4.y, u4.z, u4.w};
            #pragma unroll
            for (int j = 0; j < 4; j++) {
                int m = ch*128 + lane*4 + j;
                float d = 2.f*gg[j] - esq_r[ch][j];
                dm[ch][j] = d;
                if (d > h1v || (d == h1v && m < h1i)) { h2v = h1v; h2i = h1i; h1v = d; h1i = m; }
                else if (d > h2v || (d == h2v && m < h2i)) { h2v = d; h2i = m; }
                float sc = d + gumbel_of(uu[j]);
                if (sc > s1v || (sc == s1v && m < s1i)) { s2v = s1v; s2i = s1i; s1v = sc; s1i = m; }
                else if (sc > s2v || (sc == s2v && m < s2i)) { s2v = sc; s2i = m; }
            }
        }
        #pragma unroll
        for (int o = 16; o > 0; o >>= 1) {
            float ov1 = __shfl_xor_sync(0xffffffffu, h1v, o);
            int   oi1 = __shfl_xor_sync(0xffffffffu, h1i, o);
            float ov2 = __shfl_xor_sync(0xffffffffu, h2v, o);
            int   oi2 = __shfl_xor_sync(0xffffffffu, h2i, o);
            if (ov1 > h1v || (ov1 == h1v && oi1 < h1i)) {
                float t1v = h1v; int t1i = h1i;
                h1v = ov1; h1i = oi1;
                if (t1v > ov2 || (t1v == ov2 && t1i < oi2)) { h2v = t1v; h2i = t1i; }
                else { h2v = ov2; h2i = oi2; }
            } else {
                if (ov1 > h2v || (ov1 == h2v && oi1 < h2i)) { h2v = ov1; h2i = oi1; }
            }
            float pv1 = __shfl_xor_sync(0xffffffffu, s1v, o);
            int   pi1 = __shfl_xor_sync(0xffffffffu, s1i, o);
            float pv2 = __shfl_xor_sync(0xffffffffu, s2v, o);
            int   pi2 = __shfl_xor_sync(0xffffffffu, s2i, o);
            if (pv1 > s1v || (pv1 == s1v && pi1 < s1i)) {
                float t1v = s1v; int t1i = s1i;
                s1v = pv1; s1i = pi1;
                if (t1v > pv2 || (t1v == pv2 && t1i < pi2)) { s2v = t1v; s2i = t1i; }
                else { s2v = pv2; s2i = pi2; }
            } else {
                if (pv1 > s2v || (pv1 == s2v && pi1 < s2i)) { s2v = pv1; s2i = pi1; }
            }
        }

        int cands[4] = {h1i, h2i, s1i, s2i};
        float ex[4];
        const float* curp = g_cur + (size_t)n*DD + lane*8;
        #pragma unroll
        for (int t = 0; t < 4; t++) {
            const float* Ep = emb + (size_t)cands[t]*DD + lane*8;
            float s = 0.f;
            #pragma unroll
            for (int j = 0; j < 8; j++) s += curp[j]*Ep[j];
            #pragma unroll
            for (int o = 16; o > 0; o >>= 1) s += __shfl_xor_sync(0xffffffffu, s, o);
            ex[t] = 2.f*s - g_esq[cands[t]];
        }

        float ssum = 0.f;
        #pragma unroll
        for (int ch = 0; ch < 8; ch++)
            #pragma unroll
            for (int j = 0; j < 4; j++) { float e = __expf(dm[ch][j] - h1v); dm[ch][j] = e; ssum += e; }
        #pragma unroll
        for (int o = 16; o > 0; o >>= 1) ssum += __shfl_xor_sync(0xffffffffu, ssum, o);
        float inv = 1.f / ssum;
        #pragma unroll
        for (int ch = 0; ch < 8; ch++)
            #pragma unroll
            for (int j = 0; j < 4; j++) pAcc[ch][j] += dm[ch][j] * inv;

        if (lane == 0) {
            int kH = h1i; float vH = ex[0];
            if (ex[1] > vH || (ex[1] == vH && h2i < kH)) { kH = h2i; vH = ex[1]; }
            atomicAdd(&g_hist[kH], 1u);
            float sc0 = ex[2] + gumbel_of(Ur[s1i]);
            float sc1 = ex[3] + gumbel_of(Ur[s2i]);
            int kS = s1i;
            if (sc1 > sc0 || (sc1 == sc0 && s2i < s1i)) kS = s2i;
            g_idx[n] = kS;
            out[QSIZE + 2 + n] = (float)kS;
        }
    }
    #pragma unroll
    for (int ch = 0; ch < 8; ch++)
        #pragma unroll
        for (int j = 0; j < 4; j++) atomicAdd(&sAcc[ch*128 + lane*4 + j], pAcc[ch][j]);
    __syncthreads();
    for (int i = tid; i < MM; i += 256) atomicAdd(&g_avgp[i], sAcc[i]);
}

__global__ void k_finalize(float* __restrict__ out) {
    __shared__ float s1[MM];
    __shared__ float s2[MM];
    int m = threadIdx.x;
    float hp = (float)g_hist[m] * (1.f/(float)NN);
    float ap = g_avgp[m] * (1.f/(float)NN);
    s1[m] = -hp * log2f(hp + 1e-10f);
    s2[m] = -ap * log2f(ap + 1e-10f);
    __syncthreads();
    for (int s = 512; s > 0; s >>= 1) {
        if (m < s) { s1[m] += s1[m + s]; s2[m] += s2[m + s]; }
        __syncthreads();
    }
    if (m == 0) { out[QSIZE] = s1[0]; out[QSIZE + 1] = s2[0]; }
}

// ---------------- fuse2 (3xTF32, interleaved X, materialized W) --------------
#define F2_STG 3200
#define F2_SMEMB (64*130*4)

__global__ void __launch_bounds__(256) k_f2_tc(const float* __restrict__ a2p,
                                               float* __restrict__ out) {
    extern __shared__ float fs[];
    int tid = threadIdx.x, lane = tid & 31, warp = tid >> 5;
    int warpM = warp >> 2, warpN = warp & 3;
    int t0 = blockIdx.x*128, o0 = blockIdx.y*64, b = blockIdx.z;
    int ot0 = o0 >> 4;

    uint32_t sbase;
    asm("{ .reg .u64 t; cvta.to.shared.u64 t, %1; cvt.u32.u64 %0, t; }" : "=r"(sbase) : "l"(fs));

    auto issue = [&](int ic, int s) {
        uint32_t xd = sbase + (uint32_t)((s*F2_STG)*4);
        #pragma unroll
        for (int j = 0; j < 2; j++) {
            int idx = tid + j*256;
            int row = idx >> 6, q = idx & 63;
            const float2* sp = g_ctx2 + ((size_t)(b*DD + ic*8 + row))*TT + t0;
            asm volatile("cp.async.cg.shared.global [%0], [%1], 16;"
                :: "r"(xd + (uint32_t)((row*136 + q*2)*8)), "l"(sp + q*2));
        }
        if (tid < 128) {
            const float* wp = g_w2shh + ((size_t)ic*16 + ot0)*128;
            uint32_t wd = sbase + (uint32_t)((s*F2_STG + 2176)*4);
            asm volatile("cp.async.cg.shared.global [%0], [%1], 16;"
                :: "r"(wd + (uint32_t)(tid*16)), "l"(wp + tid*4));
        } else {
            int t2 = tid - 128;
            const float* wp = g_w2shl + ((size_t)ic*16 + ot0)*128;
            uint32_t wd = sbase + (uint32_t)((s*F2_STG + 2688)*4);
            asm volatile("cp.async.cg.shared.global [%0], [%1], 16;"
                :: "r"(wd + (uint32_t)(t2*16)), "l"(wp + t2*4));
        }
        asm volatile("cp.async.commit_group;");
    };

    float c[2][4][4] = {};
    issue(0, 0);
    issue(1, 1);

    for (int ic = 0; ic < 32; ic++) {
        int s = ic & 1;
        if (ic < 31) { asm volatile("cp.async.wait_group 1;"); }
        else         { asm volatile("cp.async.wait_group 0;"); }
        __syncthreads();
        const float2* X2 = (const float2*)(fs + s*F2_STG);
        const float* WH = fs + s*F2_STG + 2176;
        const float* WL = fs + s*F2_STG + 2688;
        int i0v = lane & 3, trow = lane >> 2;

        uint32_t ah[2][4], al[2][4];
        #pragma unroll
        for (int mf = 0; mf < 2; mf++) {
            float4 vh = *(const float4*)&WH[(warpM*2 + mf)*128 + lane*4];
            float4 vl = *(const float4*)&WL[(warpM*2 + mf)*128 + lane*4];
            ah[mf][0] = __float_as_uint(vh.x); ah[mf][1] = __float_as_uint(vh.y);
            ah[mf][2] = __float_as_uint(vh.z); ah[mf][3] = __float_as_uint(vh.w);
            al[mf][0] = __float_as_uint(vl.x); al[mf][1] = __float_as_uint(vl.y);
            al[mf][2] = __float_as_uint(vl.z); al[mf][3] = __float_as_uint(vl.w);
        }
        uint32_t bh[4][2], bl[4][2];
        #pragma unroll
        for (int nf = 0; nf < 4; nf++) {
            int toff = warpN*32 + nf*8 + trow;
            float2 v0 = X2[i0v*136 + toff];
            float2 v1 = X2[(i0v + 4)*136 + toff];
            bh[nf][0] = __float_as_uint(v0.x); bl[nf][0] = __float_as_uint(v0.y);
            bh[nf][1] = __float_as_uint(v1.x); bl[nf][1] = __float_as_uint(v1.y);
        }
        #pragma unroll
        for (int mf = 0; mf < 2; mf++) {
            #pragma unroll
            for (int nf = 0; nf < 4; nf++) {
                MMA8(c[mf][nf], ah[mf][0], ah[mf][1], ah[mf][2], ah[mf][3], bh[nf][0], bh[nf][1]);
                MMA8(c[mf][nf], ah[mf][0], ah[mf][1], ah[mf][2], ah[mf][3], bl[nf][0], bl[nf][1]);
                MMA8(c[mf][nf], al[mf][0], al[mf][1], al[mf][2], al[mf][3], bh[nf][0], bh[nf][1]);
            }
        }
        __syncthreads();
        if (ic + 2 < 32) issue(ic + 2, s);
    }

    #pragma unroll
    for (int mf = 0; mf < 2; mf++) {
        int r = warpM*32 + mf*16 + (lane >> 2);
        #pragma unroll
        for (int nf = 0; nf < 4; nf++) {
            int tg = warpN*32 + nf*8 + (lane & 3)*2;
            *(float2*)&fs[r*130 + tg]       = make_float2(c[mf][nf][0], c[mf][nf][1]);
            *(float2*)&fs[(r + 8)*130 + tg] = make_float2(c[mf][nf][2], c[mf][nf][3]);
        }
    }
    __syncthreads();
    float a2v = *a2p;
    int nl = tid >> 1, half = tid & 1;
    size_t n = (size_t)b*TT + t0 + nl;
    int mi = g_idx[n];
    const float* w2e = g_W2E + (size_t)mi*DD + o0 + half*32;
    float* op = out + n*DD + o0 + half*32;
    #pragma unroll
    for (int j = 0; j < 8; j++) {
        float4 w4 = *(const float4*)&w2e[j*4];
        float4 v;
        float u;
        u = fs[(half*32 + j*4 + 0)*130 + nl] + w4.x; v.x = (u >= 0.f) ? u : a2v*u;
        u = fs[(half*32 + j*4 + 1)*130 + nl] + w4.y; v.y = (u >= 0.f) ? u : a2v*u;
        u = fs[(half*32 + j*4 + 2)*130 + nl] + w4.z; v.z = (u >= 0.f) ? u : a2v*u;
        u = fs[(half*32 + j*4 + 3)*130 + nl] + w4.w; v.w = (u >= 0.f) ? u : a2v*u;
        *(float4*)&op[j*4] = v;
    }
}

// ---------------- launch -----------------------------------------------------
extern "C" void kernel_launch(void* const* d_in, const int* in_sizes, int n_in,
                              void* d_out, int out_size) {
    const float* x     = (const float*)d_in[0];
    const float* noise = (const float*)d_in[1];
    const float* gum   = (const float*)d_in[2];
    const int*   epo   = (const int*)  d_in[3];
    const float* emb   = (const float*)d_in[4];
    const float* wctx  = (const float*)d_in[5];
    const float* wf1   = (const float*)d_in[6];
    const float* a1    = (const float*)d_in[7];
    const float* wf2   = (const float*)d_in[8];
    const float* a2    = (const float*)d_in[9];
    float* out = (float*)d_out;

    cudaFuncSetAttribute(k_conv_tc, cudaFuncAttributeMaxDynamicSharedMemorySize, CV_SMEMB);
    cudaFuncSetAttribute(k_f1_tc, cudaFuncAttributeMaxDynamicSharedMemorySize, F1_SMEMB);
    cudaFuncSetAttribute(k_dist_b, cudaFuncAttributeMaxDynamicSharedMemorySize, DB_SMEMB);
    cudaFuncSetAttribute(k_f2_tc, cudaFuncAttributeMaxDynamicSharedMemorySize, F2_SMEMB);

    dim3 tb32(32, 8);

    k_scale<<<BB, 256>>>(x, epo);                                   // 0
    k_noisy<<<dim3((LL + 31)/32, DD/32, BB), tb32>>>(x, noise);     // 1
    k_prep_w<<<2560, 256>>>(wctx, wf1, wf2);                        // 2
    k_conv_tc<<<dim3(TT/256, 4, BB), 256, CV_SMEMB>>>();            // 3 <- capture
    k_xt<<<dim3(TT/32, DD/32, BB), tb32>>>(x);
    k_f1_tc<<<dim3(TT/128, DD/64, BB), 256, F1_SMEMB>>>(a1);
    k_transp<<<dim3(DD/32, MM/32), tb32>>>(emb, MM, DD, 0);         // ET
    k_transp<<<dim3(2*DD/32, DD/32), tb32>>>(wf2, DD, 2*DD, 1);     // w2T
    k_prep_e<<<MM, 256>>>(emb);
    k_gemm_w2e<<<dim3(MM/64, DD/64), 256>>>();
    k_dist_b<<<dim3(NN/128, MM/128), 256, DB_SMEMB>>>();
    k_rowstats<<<NN/16, 256>>>(gum, emb, out);
    k_finalize<<<1, MM>>>(out);
    k_f2_tc<<<dim3(TT/128, DD/64, BB), 256, F2_SMEMB>>>(a2, out);
}